// round 11
// baseline (speedup 1.0000x reference)
#include <cuda_runtime.h>
#include <cuda_fp16.h>
#include <cstdint>
#include <cstddef>

// Problem constants
#define T_TOK   4096
#define HDIM    1024
#define IDIM    2048
#define NEXP    8
#define TOPK    2
#define NROWS_ROUTED (T_TOK * TOPK)         // 8192
#define NROWS_TOTAL  (NROWS_ROUTED + T_TOK) // 12288
#define ROUTER_BLOCKS (T_TOK / 8)           // 512

#define OUT_AUX    (T_TOK * HDIM)
#define OUT_Z      (OUT_AUX + 1)
#define OUT_LOGITS (OUT_AUX + 2)

// ---------------- scratch ----------------------------------------------------
__device__ int   g_count[NEXP];
__device__ int   g_list[NEXP * T_TOK];
__device__ float g_wgt [NEXP * T_TOK];
__device__ int   g_rowbase[NEXP + 1];
__device__ int   g_ctok[NROWS_TOTAL];
__device__ float g_cwgt[NROWS_TOTAL];
__device__ float g_pp[ROUTER_BLOCKS * NEXP];
__device__ float g_pl[ROUTER_BLOCKS];

// fp16 operands (16B-aligned for cp.async)
__device__ __align__(16) __half g_Xh [(size_t)T_TOK * HDIM];
__device__ __align__(16) __half g_Gh [(size_t)NROWS_TOTAL * IDIM];
__device__ __align__(16) __half g_gWt[(size_t)NEXP * IDIM * HDIM];  // [e][N][K]
__device__ __align__(16) __half g_uWt[(size_t)NEXP * IDIM * HDIM];
__device__ __align__(16) __half g_dWt[(size_t)NEXP * HDIM * IDIM];
__device__ __align__(16) __half g_sgWt[(size_t)IDIM * HDIM];
__device__ __align__(16) __half g_suWt[(size_t)IDIM * HDIM];
__device__ __align__(16) __half g_sdWt[(size_t)HDIM * IDIM];

// ---------------- helpers -----------------------------------------------------
__device__ __forceinline__ void cp_async16(uint32_t s, const void* g) {
    asm volatile("cp.async.cg.shared.global [%0], [%1], 16;\n" :: "r"(s), "l"(g));
}
__device__ __forceinline__ void cp_commit() {
    asm volatile("cp.async.commit_group;\n");
}
template <int N>
__device__ __forceinline__ void cp_wait() {
    asm volatile("cp.async.wait_group %0;\n" :: "n"(N));
}
__device__ __forceinline__ void mma_f16(float* d, const uint32_t* a, const uint32_t* b) {
    asm volatile(
        "mma.sync.aligned.m16n8k16.row.col.f32.f16.f16.f32 "
        "{%0,%1,%2,%3},{%4,%5,%6,%7},{%8,%9},{%0,%1,%2,%3};"
        : "+f"(d[0]), "+f"(d[1]), "+f"(d[2]), "+f"(d[3])
        : "r"(a[0]), "r"(a[1]), "r"(a[2]), "r"(a[3]), "r"(b[0]), "r"(b[1]));
}

// ---------------- router (+ fused X->fp16 conversion) -------------------------
__global__ void __launch_bounds__(256) router_kernel(
    const float* __restrict__ x, const float* __restrict__ rw,
    float* __restrict__ out)
{
    const int warp = threadIdx.x >> 5, lane = threadIdx.x & 31;
    const int t = blockIdx.x * 8 + warp;

    float acc[NEXP];
#pragma unroll
    for (int e = 0; e < NEXP; e++) acc[e] = 0.f;

    const float* xr = x + (size_t)t * HDIM;
    for (int h = lane; h < HDIM; h += 32) {
        float xv = xr[h];
        const float* r = rw + (size_t)h * NEXP;
#pragma unroll
        for (int e = 0; e < NEXP; e++) acc[e] += xv * r[e];
    }
    // fused fp16 conversion of this token's row (L2-hot)
    {
        __half2* dst = (__half2*)(g_Xh + (size_t)t * HDIM);
        for (int h = lane; h < HDIM / 2; h += 32) {
            float2 v = *(const float2*)(xr + 2 * h);
            dst[h] = __floats2half2_rn(v.x, v.y);
        }
    }
#pragma unroll
    for (int off = 16; off > 0; off >>= 1)
#pragma unroll
        for (int e = 0; e < NEXP; e++)
            acc[e] += __shfl_xor_sync(0xFFFFFFFFu, acc[e], off);

    __shared__ float s_prob[8][NEXP];
    __shared__ float s_lse2[8];

    if (lane == 0) {
        float mx = acc[0];
#pragma unroll
        for (int e = 1; e < NEXP; e++) mx = fmaxf(mx, acc[e]);
        float p[NEXP], sum = 0.f;
#pragma unroll
        for (int e = 0; e < NEXP; e++) { p[e] = expf(acc[e] - mx); sum += p[e]; }
        float lse = logf(sum) + mx;
        s_lse2[warp] = lse * lse;
        float inv = 1.f / sum;
#pragma unroll
        for (int e = 0; e < NEXP; e++) {
            p[e] *= inv;
            s_prob[warp][e] = p[e];
            out[OUT_LOGITS + (size_t)t * NEXP + e] = acc[e];
        }
        int i1 = 0;
#pragma unroll
        for (int e = 1; e < NEXP; e++) if (p[e] > p[i1]) i1 = e;
        int i2 = (i1 == 0) ? 1 : 0;
#pragma unroll
        for (int e = 0; e < NEXP; e++) if (e != i2 && e != i1 && p[e] > p[i2]) i2 = e;
        float s2 = p[i1] + p[i2];
        float w1 = p[i1] / s2, w2 = p[i2] / s2;
        int pos1 = atomicAdd(&g_count[i1], 1);
        g_list[i1 * T_TOK + pos1] = t; g_wgt[i1 * T_TOK + pos1] = w1;
        int pos2 = atomicAdd(&g_count[i2], 1);
        g_list[i2 * T_TOK + pos2] = t; g_wgt[i2 * T_TOK + pos2] = w2;
    }
    __syncthreads();
    if (threadIdx.x == 0) {
        float ps[NEXP]; float l2 = 0.f;
#pragma unroll
        for (int e = 0; e < NEXP; e++) ps[e] = 0.f;
        for (int w = 0; w < 8; w++) {
            l2 += s_lse2[w];
#pragma unroll
            for (int e = 0; e < NEXP; e++) ps[e] += s_prob[w][e];
        }
#pragma unroll
        for (int e = 0; e < NEXP; e++) g_pp[blockIdx.x * NEXP + e] = ps[e];
        g_pl[blockIdx.x] = l2;
    }
}

// ---------------- finalize ----------------------------------------------------
__global__ void finalize_kernel(float* __restrict__ out) {
    const int warp = threadIdx.x >> 5, lane = threadIdx.x & 31;
    __shared__ float red[NEXP + 1];
    if (warp < NEXP) {
        float s = 0.f;
        for (int j = 0; j < ROUTER_BLOCKS / 32; j++)
            s += g_pp[(size_t)(lane + 32 * j) * NEXP + warp];
#pragma unroll
        for (int off = 16; off > 0; off >>= 1) s += __shfl_xor_sync(0xFFFFFFFFu, s, off);
        if (lane == 0) red[warp] = s;
    } else if (warp == NEXP) {
        float s = 0.f;
        for (int j = 0; j < ROUTER_BLOCKS / 32; j++)
            s += g_pl[lane + 32 * j];
#pragma unroll
        for (int off = 16; off > 0; off >>= 1) s += __shfl_xor_sync(0xFFFFFFFFu, s, off);
        if (lane == 0) red[NEXP] = s;
    }
    __syncthreads();
    if (threadIdx.x == 0) {
        float aux = 0.f;
        int rb = 0;
        for (int e = 0; e < NEXP; e++) {
            aux += ((float)g_count[e] / (float)(T_TOK * TOPK)) * (red[e] / (float)T_TOK);
            g_rowbase[e] = rb;
            rb += g_count[e];
        }
        g_rowbase[NEXP] = NROWS_ROUTED;
        out[OUT_AUX] = (float)NEXP * aux;
        out[OUT_Z]   = red[NEXP] / (float)T_TOK;
    }
}

// ---------------- compact -----------------------------------------------------
__global__ void compact_kernel() {
    int idx = blockIdx.x * blockDim.x + threadIdx.x;
    int e = idx / T_TOK, pos = idx % T_TOK;
    if (e < NEXP) {
        if (pos < g_count[e]) {
            int cr = g_rowbase[e] + pos;
            g_ctok[cr] = g_list[e * T_TOK + pos];
            g_cwgt[cr] = g_wgt[e * T_TOK + pos];
        }
    } else {
        g_ctok[NROWS_ROUTED + pos] = pos;
        g_cwgt[NROWS_ROUTED + pos] = 1.f;
    }
}

// ---------------- batched transpose+cvt: [K][N] f32 -> [N][K] fp16 ------------
__device__ __forceinline__ void transpose_tile(
    const float* __restrict__ src, __half* __restrict__ dst, int K, int N,
    int n0, int k0, int tx, int ty)
{
    __shared__ float t[32][33];
#pragma unroll
    for (int i = 0; i < 32; i += 8)
        t[ty + i][tx] = src[(size_t)(k0 + ty + i) * N + n0 + tx];
    __syncthreads();
#pragma unroll
    for (int i = 0; i < 32; i += 8)
        dst[(size_t)(n0 + ty + i) * K + k0 + tx] = __float2half_rn(t[tx][ty + i]);
}

__global__ void cvt_gu_w_kernel(const float* __restrict__ gate_w,
                                const float* __restrict__ up_w,
                                const float* __restrict__ sg_w,
                                const float* __restrict__ su_w)
{
    const int z = blockIdx.z;
    const float* src; __half* dst;
    if (z < 8)       { src = gate_w + (size_t)z * HDIM * IDIM;        dst = g_gWt + (size_t)z * IDIM * HDIM; }
    else if (z < 16) { src = up_w   + (size_t)(z - 8) * HDIM * IDIM;  dst = g_uWt + (size_t)(z - 8) * IDIM * HDIM; }
    else if (z == 16){ src = sg_w;  dst = g_sgWt; }
    else             { src = su_w;  dst = g_suWt; }
    transpose_tile(src, dst, HDIM, IDIM, blockIdx.x * 32, blockIdx.y * 32,
                   threadIdx.x, threadIdx.y);
}
__global__ void cvt_dn_w_kernel(const float* __restrict__ down_w,
                                const float* __restrict__ sd_w)
{
    const int z = blockIdx.z;
    const float* src; __half* dst;
    if (z < 8) { src = down_w + (size_t)z * IDIM * HDIM; dst = g_dWt + (size_t)z * HDIM * IDIM; }
    else       { src = sd_w;  dst = g_sdWt; }
    transpose_tile(src, dst, IDIM, HDIM, blockIdx.x * 32, blockIdx.y * 32,
                   threadIdx.x, threadIdx.y);
}

// ============================================================================
// fp16 fused gate+up+act GEMM. 512 thr (16 warps, 4m x 4n), block 128x128,
// warp 32x32 each. K-tile 64, 3-stage cp.async pipeline, one barrier per kt.
// ============================================================================
#define PADH 72
#define TILE_H (128 * PADH)
#define NSTG 3
#define GU_SMEMB (NSTG * 3 * TILE_H * 2)   // 165888 B
#define DN_SMEMB (NSTG * 2 * TILE_H * 2)   // 110592 B

__global__ void __launch_bounds__(512, 1) gemm_gu_f16(void)
{
    const int e = blockIdx.z;
    const int n_e = (e < NEXP) ? g_count[e] : T_TOK;
    const int m0 = blockIdx.y * 128;
    if (m0 >= n_e) return;
    const int base = g_rowbase[e];
    const __half* __restrict__ Bg = (e < NEXP) ? (g_gWt + (size_t)e * IDIM * HDIM) : g_sgWt;
    const __half* __restrict__ Bu = (e < NEXP) ? (g_uWt + (size_t)e * IDIM * HDIM) : g_suWt;
    const int n0 = blockIdx.x * 128;

    const int tid  = threadIdx.x;
    const int warp = tid >> 5, lane = tid & 31;
    const int gi = lane >> 2, tig = lane & 3;
    const int wm = (warp & 3) * 32, wn = (warp >> 2) * 32;

    extern __shared__ __half sh[];
    __half* As  = sh;
    __half* Bgs = sh + NSTG * TILE_H;
    __half* Bus = sh + 2 * NSTG * TILE_H;
    const uint32_t uA = (uint32_t)__cvta_generic_to_shared(As);
    const uint32_t uG = (uint32_t)__cvta_generic_to_shared(Bgs);
    const uint32_t uU = (uint32_t)__cvta_generic_to_shared(Bus);

    const int pr0 = tid >> 3, pch = tid & 7;
    const __half* arow0;
    const __half* arow1;
    {
        int t0 = (m0 + pr0 < n_e)      ? g_ctok[base + m0 + pr0]      : g_ctok[base];
        int t1 = (m0 + pr0 + 64 < n_e) ? g_ctok[base + m0 + pr0 + 64] : g_ctok[base];
        arow0 = g_Xh + (size_t)t0 * HDIM + pch * 8;
        arow1 = g_Xh + (size_t)t1 * HDIM + pch * 8;
    }
    const __half* bgrow = Bg + (size_t)(n0 + pr0) * HDIM + pch * 8;
    const __half* burow = Bu + (size_t)(n0 + pr0) * HDIM + pch * 8;
    const size_t BROW64 = (size_t)64 * HDIM;
    const uint32_t d0 = (uint32_t)(pr0 * PADH + pch * 8) * 2;
    const uint32_t d1 = d0 + (uint32_t)(64 * PADH) * 2;

    float dg[2][4][4], du[2][4][4];
#pragma unroll
    for (int i = 0; i < 2; i++)
#pragma unroll
        for (int j = 0; j < 4; j++)
#pragma unroll
            for (int c = 0; c < 4; c++) { dg[i][j][c] = 0.f; du[i][j][c] = 0.f; }

    auto issue = [&](int kt, int s) {
        const int ko = kt * 64;
        const uint32_t bo = (uint32_t)(s * TILE_H * 2);
        cp_async16(uA + bo + d0, arow0 + ko);
        cp_async16(uA + bo + d1, arow1 + ko);
        cp_async16(uG + bo + d0, bgrow + ko);
        cp_async16(uG + bo + d1, bgrow + BROW64 + ko);
        cp_async16(uU + bo + d0, burow + ko);
        cp_async16(uU + bo + d1, burow + BROW64 + ko);
        cp_commit();
    };

    const int NK = HDIM / 64;   // 16
    issue(0, 0);
    issue(1, 1);
    int sbuf = 0;
    for (int kt = 0; kt < NK; kt++) {
        if (kt + 1 < NK) cp_wait<1>(); else cp_wait<0>();
        __syncthreads();
        if (kt + 2 < NK) {
            int s2 = sbuf + 2; if (s2 >= NSTG) s2 -= NSTG;
            issue(kt + 2, s2);
        }
        const __half* Ab = As  + sbuf * TILE_H;
        const __half* Gb = Bgs + sbuf * TILE_H;
        const __half* Ub = Bus + sbuf * TILE_H;
#pragma unroll
        for (int ks = 0; ks < 4; ks++) {
            const int kc = ks * 16 + 2 * tig;
            uint32_t af[2][4];
#pragma unroll
            for (int ms = 0; ms < 2; ms++) {
                const int mB = wm + ms * 16;
                af[ms][0] = *(const uint32_t*)&Ab[(mB + gi)     * PADH + kc];
                af[ms][1] = *(const uint32_t*)&Ab[(mB + 8 + gi) * PADH + kc];
                af[ms][2] = *(const uint32_t*)&Ab[(mB + gi)     * PADH + kc + 8];
                af[ms][3] = *(const uint32_t*)&Ab[(mB + 8 + gi) * PADH + kc + 8];
            }
            uint32_t bf[4][2];
#pragma unroll
            for (int ns = 0; ns < 4; ns++) {
                const int nB = wn + ns * 8 + gi;
                bf[ns][0] = *(const uint32_t*)&Gb[nB * PADH + kc];
                bf[ns][1] = *(const uint32_t*)&Gb[nB * PADH + kc + 8];
            }
#pragma unroll
            for (int ms = 0; ms < 2; ms++)
#pragma unroll
                for (int ns = 0; ns < 4; ns++)
                    mma_f16(dg[ms][ns], af[ms], bf[ns]);
#pragma unroll
            for (int ns = 0; ns < 4; ns++) {
                const int nB = wn + ns * 8 + gi;
                bf[ns][0] = *(const uint32_t*)&Ub[nB * PADH + kc];
                bf[ns][1] = *(const uint32_t*)&Ub[nB * PADH + kc + 8];
            }
#pragma unroll
            for (int ms = 0; ms < 2; ms++)
#pragma unroll
                for (int ns = 0; ns < 4; ns++)
                    mma_f16(du[ms][ns], af[ms], bf[ns]);
        }
        if (++sbuf == NSTG) sbuf = 0;
    }

#pragma unroll
    for (int ms = 0; ms < 2; ms++) {
#pragma unroll
        for (int hh = 0; hh < 2; hh++) {
            const int r = m0 + wm + ms * 16 + hh * 8 + gi;
            if (r < n_e) {
                const int row = base + r;
                const float w = g_cwgt[row];
                __half* C = g_Gh + (size_t)row * IDIM + n0 + wn;
#pragma unroll
                for (int ns = 0; ns < 4; ns++) {
                    float g0 = dg[ms][ns][2 * hh],     g1 = dg[ms][ns][2 * hh + 1];
                    float u0 = du[ms][ns][2 * hh],     u1 = du[ms][ns][2 * hh + 1];
                    float h0 = w * u0 * g0 / (1.f + __expf(-g0));
                    float h1 = w * u1 * g1 / (1.f + __expf(-g1));
                    *(__half2*)(C + ns * 8 + 2 * tig) = __floats2half2_rn(h0, h1);
                }
            }
        }
    }
}

// ============================================================================
// fp16 down GEMM + scatter. 256 thr (8 warps, 4m x 2n), warp 32x64,
// 2 CTAs/SM. K-tile 64, 3-stage pipeline, one barrier per kt.
// ============================================================================
__global__ void __launch_bounds__(256, 2) gemm_down_f16(float* __restrict__ out)
{
    const int e = blockIdx.z;
    const int n_e = (e < NEXP) ? g_count[e] : T_TOK;
    const int m0 = blockIdx.y * 128;
    if (m0 >= n_e) return;
    const int base = g_rowbase[e];
    const __half* __restrict__ B = (e < NEXP) ? (g_dWt + (size_t)e * HDIM * IDIM) : g_sdWt;
    const int n0 = blockIdx.x * 128;

    const int tid  = threadIdx.x;
    const int warp = tid >> 5, lane = tid & 31;
    const int gi = lane >> 2, tig = lane & 3;
    const int wm = (warp & 3) * 32, wn = (warp >> 2) * 64;

    extern __shared__ __half sh[];
    __half* As = sh;
    __half* Bs = sh + NSTG * TILE_H;
    const uint32_t uA = (uint32_t)__cvta_generic_to_shared(As);
    const uint32_t uB = (uint32_t)__cvta_generic_to_shared(Bs);

    const int pr0 = tid >> 3, pch = tid & 7;
    const __half* arow = g_Gh + (size_t)(base + m0 + pr0) * IDIM + pch * 8;
    const __half* brow = B + (size_t)(n0 + pr0) * IDIM + pch * 8;
    const size_t ROW32 = (size_t)32 * IDIM;
    const uint32_t ds0 = (uint32_t)(pr0 * PADH + pch * 8) * 2;
    const uint32_t SROW32 = (uint32_t)(32 * PADH) * 2;

    float d[2][8][4];
#pragma unroll
    for (int i = 0; i < 2; i++)
#pragma unroll
        for (int j = 0; j < 8; j++)
#pragma unroll
            for (int c = 0; c < 4; c++) d[i][j][c] = 0.f;

    auto issue = [&](int kt, int s) {
        const int ko = kt * 64;
        const uint32_t bo = (uint32_t)(s * TILE_H * 2);
#pragma unroll
        for (int c = 0; c < 4; c++) {
            cp_async16(uA + bo + ds0 + c * SROW32, arow + c * ROW32 + ko);
            cp_async16(uB + bo + ds0 + c * SROW32, brow + c * ROW32 + ko);
        }
        cp_commit();
    };

    const int NK = IDIM / 64;   // 32
    issue(0, 0);
    issue(1, 1);
    int sbuf = 0;
    for (int kt = 0; kt < NK; kt++) {
        if (kt + 1 < NK) cp_wait<1>(); else cp_wait<0>();
        __syncthreads();
        if (kt + 2 < NK) {
            int s2 = sbuf + 2; if (s2 >= NSTG) s2 -= NSTG;
            issue(kt + 2, s2);
        }
        const __half* Ab = As + sbuf * TILE_H;
        const __half* Bb = Bs + sbuf * TILE_H;
#pragma unroll
        for (int ks = 0; ks < 4; ks++) {
            const int kc = ks * 16 + 2 * tig;
            uint32_t af[2][4];
#pragma unroll
            for (int ms = 0; ms < 2; ms++) {
                const int mB = wm + ms * 16;
                af[ms][0] = *(const uint32_t*)&Ab[(mB + gi)     * PADH + kc];
                af[ms][1] = *(const uint32_t*)&Ab[(mB + 8 + gi) * PADH + kc];
                af[ms][2] = *(const uint32_t*)&Ab[(mB + gi)     * PADH + kc + 8];
                af[ms][3] = *(const uint32_t*)&Ab[(mB + 8 + gi) * PADH + kc + 8];
            }
            uint32_t bf[8][2];
#pragma unroll
            for (int ns = 0; ns < 8; ns++) {
                const int nB = wn + ns * 8 + gi;
                bf[ns][0] = *(const uint32_t*)&Bb[nB * PADH + kc];
                bf[ns][1] = *(const uint32_t*)&Bb[nB * PADH + kc + 8];
            }
#pragma unroll
            for (int ms = 0; ms < 2; ms++)
#pragma unroll
                for (int ns = 0; ns < 8; ns++)
                    mma_f16(d[ms][ns], af[ms], bf[ns]);
        }
        if (++sbuf == NSTG) sbuf = 0;
    }

#pragma unroll
    for (int ms = 0; ms < 2; ms++) {
        const int r0 = m0 + wm + ms * 16 + gi;
        const int r1 = r0 + 8;
        if (r0 < n_e) {
            const int tok = g_ctok[base + r0];
            float* o = out + (size_t)tok * HDIM + n0 + wn;
#pragma unroll
            for (int ns = 0; ns < 8; ns++) {
                atomicAdd(o + ns * 8 + 2 * tig,     d[ms][ns][0]);
                atomicAdd(o + ns * 8 + 2 * tig + 1, d[ms][ns][1]);
            }
        }
        if (r1 < n_e) {
            const int tok = g_ctok[base + r1];
            float* o = out + (size_t)tok * HDIM + n0 + wn;
#pragma unroll
            for (int ns = 0; ns < 8; ns++) {
                atomicAdd(o + ns * 8 + 2 * tig,     d[ms][ns][2]);
                atomicAdd(o + ns * 8 + 2 * tig + 1, d[ms][ns][3]);
            }
        }
    }
}

// ---------------- host launcher ----------------------------------------------
extern "C" void kernel_launch(void* const* d_in, const int* in_sizes, int n_in,
                              void* d_out, int out_size)
{
    const float* x       = (const float*)d_in[0];
    const float* rw      = (const float*)d_in[1];
    const float* gate_w  = (const float*)d_in[2];
    const float* up_w    = (const float*)d_in[3];
    const float* down_w  = (const float*)d_in[4];
    const float* sgate_w = (const float*)d_in[5];
    const float* sup_w   = (const float*)d_in[6];
    const float* sdown_w = (const float*)d_in[7];
    float* out = (float*)d_out;

    // one-time host-side objects (no device memory allocation). Created during
    // the first (eager) call; reused as-is during graph capture. GPU work is
    // identical every call; if creation failed, fall back to single-stream.
    static cudaStream_t s1 = nullptr;
    static cudaEvent_t evFork = nullptr, evJoinGu = nullptr, evJoinDn = nullptr;
    static bool init_tried = false;
    if (!init_tried) {
        init_tried = true;
        if (cudaStreamCreateWithFlags(&s1, cudaStreamNonBlocking) != cudaSuccess) s1 = nullptr;
        if (s1) {
            if (cudaEventCreateWithFlags(&evFork,   cudaEventDisableTiming) != cudaSuccess ||
                cudaEventCreateWithFlags(&evJoinGu, cudaEventDisableTiming) != cudaSuccess ||
                cudaEventCreateWithFlags(&evJoinDn, cudaEventDisableTiming) != cudaSuccess)
                s1 = nullptr;
        }
    }

    void* cnt_addr = nullptr;
    cudaGetSymbolAddress(&cnt_addr, g_count);

    cudaFuncSetAttribute(gemm_gu_f16,
                         cudaFuncAttributeMaxDynamicSharedMemorySize, GU_SMEMB);
    cudaFuncSetAttribute(gemm_down_f16,
                         cudaFuncAttributeMaxDynamicSharedMemorySize, DN_SMEMB);

    dim3 tb(32, 8);
    dim3 grid_gu(IDIM / 128, T_TOK / 128, NEXP + 1);
    dim3 grid_dn(HDIM / 128, T_TOK / 128, NEXP + 1);

    if (s1) {
        // fork side stream for the weight-conversion passes
        cudaEventRecord(evFork, 0);
        cudaStreamWaitEvent(s1, evFork, 0);
        cvt_gu_w_kernel<<<dim3(IDIM / 32, HDIM / 32, 18), tb, 0, s1>>>(
            gate_w, up_w, sgate_w, sup_w);
        cudaEventRecord(evJoinGu, s1);
        cvt_dn_w_kernel<<<dim3(HDIM / 32, IDIM / 32, 9), tb, 0, s1>>>(
            down_w, sdown_w);
        cudaEventRecord(evJoinDn, s1);

        // main stream: routing chain (overlaps with cvt_gu)
        cudaMemsetAsync(out, 0, (size_t)T_TOK * HDIM * sizeof(float));
        cudaMemsetAsync(cnt_addr, 0, NEXP * sizeof(int));
        router_kernel<<<ROUTER_BLOCKS, 256>>>(x, rw, out);
        finalize_kernel<<<1, 288>>>(out);
        compact_kernel<<<((NEXP + 1) * T_TOK) / 256, 256>>>();

        cudaStreamWaitEvent(0, evJoinGu, 0);      // gu needs converted gu weights
        gemm_gu_f16<<<grid_gu, 512, GU_SMEMB>>>();

        cudaStreamWaitEvent(0, evJoinDn, 0);      // down needs converted dn weights
        gemm_down_f16<<<grid_dn, 256, DN_SMEMB>>>(out);
    } else {
        // fallback: single-stream (identical to previous round's schedule)
        cudaMemsetAsync(out, 0, (size_t)T_TOK * HDIM * sizeof(float));
        cudaMemsetAsync(cnt_addr, 0, NEXP * sizeof(int));
        router_kernel<<<ROUTER_BLOCKS, 256>>>(x, rw, out);
        finalize_kernel<<<1, 288>>>(out);
        compact_kernel<<<((NEXP + 1) * T_TOK) / 256, 256>>>();
        cvt_gu_w_kernel<<<dim3(IDIM / 32, HDIM / 32, 18), tb>>>(gate_w, up_w, sgate_w, sup_w);
        cvt_dn_w_kernel<<<dim3(HDIM / 32, IDIM / 32, 9),  tb>>>(down_w, sdown_w);
        gemm_gu_f16<<<grid_gu, 512, GU_SMEMB>>>();
        gemm_down_f16<<<grid_dn, 256, DN_SMEMB>>>(out);
    }
}

// round 12
// speedup vs baseline: 1.0244x; 1.0244x over previous
#include <cuda_runtime.h>
#include <cuda_fp16.h>
#include <cstdint>
#include <cstddef>

// Problem constants
#define T_TOK   4096
#define HDIM    1024
#define IDIM    2048
#define NEXP    8
#define TOPK    2
#define NROWS_ROUTED (T_TOK * TOPK)         // 8192
#define NROWS_TOTAL  (NROWS_ROUTED + T_TOK) // 12288
#define ROUTER_BLOCKS (T_TOK / 8)           // 512

#define OUT_AUX    (T_TOK * HDIM)
#define OUT_Z      (OUT_AUX + 1)
#define OUT_LOGITS (OUT_AUX + 2)

// ---------------- scratch ----------------------------------------------------
__device__ int   g_count[NEXP];
__device__ int   g_list[NEXP * T_TOK];
__device__ float g_wgt [NEXP * T_TOK];
__device__ int   g_rowbase[NEXP + 1];
__device__ int   g_ctok[NROWS_TOTAL];
__device__ float g_cwgt[NROWS_TOTAL];
__device__ float g_pp[ROUTER_BLOCKS * NEXP];
__device__ float g_pl[ROUTER_BLOCKS];

// fp16 operands (16B-aligned for cp.async)
__device__ __align__(16) __half g_Xh [(size_t)T_TOK * HDIM];
__device__ __align__(16) __half g_Gh [(size_t)NROWS_TOTAL * IDIM];
__device__ __align__(16) __half g_gWt[(size_t)NEXP * IDIM * HDIM];  // [e][N][K]
__device__ __align__(16) __half g_uWt[(size_t)NEXP * IDIM * HDIM];
__device__ __align__(16) __half g_dWt[(size_t)NEXP * HDIM * IDIM];
__device__ __align__(16) __half g_sgWt[(size_t)IDIM * HDIM];
__device__ __align__(16) __half g_suWt[(size_t)IDIM * HDIM];
__device__ __align__(16) __half g_sdWt[(size_t)HDIM * IDIM];

// ---------------- helpers -----------------------------------------------------
__device__ __forceinline__ void cp_async16(uint32_t s, const void* g) {
    asm volatile("cp.async.cg.shared.global [%0], [%1], 16;\n" :: "r"(s), "l"(g));
}
__device__ __forceinline__ void cp_commit() {
    asm volatile("cp.async.commit_group;\n");
}
template <int N>
__device__ __forceinline__ void cp_wait() {
    asm volatile("cp.async.wait_group %0;\n" :: "n"(N));
}
__device__ __forceinline__ void mma_f16(float* d, const uint32_t* a, const uint32_t* b) {
    asm volatile(
        "mma.sync.aligned.m16n8k16.row.col.f32.f16.f16.f32 "
        "{%0,%1,%2,%3},{%4,%5,%6,%7},{%8,%9},{%0,%1,%2,%3};"
        : "+f"(d[0]), "+f"(d[1]), "+f"(d[2]), "+f"(d[3])
        : "r"(a[0]), "r"(a[1]), "r"(a[2]), "r"(a[3]), "r"(b[0]), "r"(b[1]));
}

// ---------------- router (+ fused X->fp16 conversion) -------------------------
__global__ void __launch_bounds__(256) router_kernel(
    const float* __restrict__ x, const float* __restrict__ rw,
    float* __restrict__ out)
{
    const int warp = threadIdx.x >> 5, lane = threadIdx.x & 31;
    const int t = blockIdx.x * 8 + warp;

    float acc[NEXP];
#pragma unroll
    for (int e = 0; e < NEXP; e++) acc[e] = 0.f;

    const float* xr = x + (size_t)t * HDIM;
    for (int h = lane; h < HDIM; h += 32) {
        float xv = xr[h];
        const float* r = rw + (size_t)h * NEXP;
#pragma unroll
        for (int e = 0; e < NEXP; e++) acc[e] += xv * r[e];
    }
    // fused fp16 conversion of this token's row (L2-hot)
    {
        __half2* dst = (__half2*)(g_Xh + (size_t)t * HDIM);
        for (int h = lane; h < HDIM / 2; h += 32) {
            float2 v = *(const float2*)(xr + 2 * h);
            dst[h] = __floats2half2_rn(v.x, v.y);
        }
    }
#pragma unroll
    for (int off = 16; off > 0; off >>= 1)
#pragma unroll
        for (int e = 0; e < NEXP; e++)
            acc[e] += __shfl_xor_sync(0xFFFFFFFFu, acc[e], off);

    __shared__ float s_prob[8][NEXP];
    __shared__ float s_lse2[8];

    if (lane == 0) {
        float mx = acc[0];
#pragma unroll
        for (int e = 1; e < NEXP; e++) mx = fmaxf(mx, acc[e]);
        float p[NEXP], sum = 0.f;
#pragma unroll
        for (int e = 0; e < NEXP; e++) { p[e] = expf(acc[e] - mx); sum += p[e]; }
        float lse = logf(sum) + mx;
        s_lse2[warp] = lse * lse;
        float inv = 1.f / sum;
#pragma unroll
        for (int e = 0; e < NEXP; e++) {
            p[e] *= inv;
            s_prob[warp][e] = p[e];
            out[OUT_LOGITS + (size_t)t * NEXP + e] = acc[e];
        }
        int i1 = 0;
#pragma unroll
        for (int e = 1; e < NEXP; e++) if (p[e] > p[i1]) i1 = e;
        int i2 = (i1 == 0) ? 1 : 0;
#pragma unroll
        for (int e = 0; e < NEXP; e++) if (e != i2 && e != i1 && p[e] > p[i2]) i2 = e;
        float s2 = p[i1] + p[i2];
        float w1 = p[i1] / s2, w2 = p[i2] / s2;
        int pos1 = atomicAdd(&g_count[i1], 1);
        g_list[i1 * T_TOK + pos1] = t; g_wgt[i1 * T_TOK + pos1] = w1;
        int pos2 = atomicAdd(&g_count[i2], 1);
        g_list[i2 * T_TOK + pos2] = t; g_wgt[i2 * T_TOK + pos2] = w2;
    }
    __syncthreads();
    if (threadIdx.x == 0) {
        float ps[NEXP]; float l2 = 0.f;
#pragma unroll
        for (int e = 0; e < NEXP; e++) ps[e] = 0.f;
        for (int w = 0; w < 8; w++) {
            l2 += s_lse2[w];
#pragma unroll
            for (int e = 0; e < NEXP; e++) ps[e] += s_prob[w][e];
        }
#pragma unroll
        for (int e = 0; e < NEXP; e++) g_pp[blockIdx.x * NEXP + e] = ps[e];
        g_pl[blockIdx.x] = l2;
    }
}

// ---------------- finalize ----------------------------------------------------
__global__ void finalize_kernel(float* __restrict__ out) {
    const int warp = threadIdx.x >> 5, lane = threadIdx.x & 31;
    __shared__ float red[NEXP + 1];
    if (warp < NEXP) {
        float s = 0.f;
        for (int j = 0; j < ROUTER_BLOCKS / 32; j++)
            s += g_pp[(size_t)(lane + 32 * j) * NEXP + warp];
#pragma unroll
        for (int off = 16; off > 0; off >>= 1) s += __shfl_xor_sync(0xFFFFFFFFu, s, off);
        if (lane == 0) red[warp] = s;
    } else if (warp == NEXP) {
        float s = 0.f;
        for (int j = 0; j < ROUTER_BLOCKS / 32; j++)
            s += g_pl[lane + 32 * j];
#pragma unroll
        for (int off = 16; off > 0; off >>= 1) s += __shfl_xor_sync(0xFFFFFFFFu, s, off);
        if (lane == 0) red[NEXP] = s;
    }
    __syncthreads();
    if (threadIdx.x == 0) {
        float aux = 0.f;
        int rb = 0;
        for (int e = 0; e < NEXP; e++) {
            aux += ((float)g_count[e] / (float)(T_TOK * TOPK)) * (red[e] / (float)T_TOK);
            g_rowbase[e] = rb;
            rb += g_count[e];
        }
        g_rowbase[NEXP] = NROWS_ROUTED;
        out[OUT_AUX] = (float)NEXP * aux;
        out[OUT_Z]   = red[NEXP] / (float)T_TOK;
    }
}

// ---------------- compact -----------------------------------------------------
__global__ void compact_kernel() {
    int idx = blockIdx.x * blockDim.x + threadIdx.x;
    int e = idx / T_TOK, pos = idx % T_TOK;
    if (e < NEXP) {
        if (pos < g_count[e]) {
            int cr = g_rowbase[e] + pos;
            g_ctok[cr] = g_list[e * T_TOK + pos];
            g_cwgt[cr] = g_wgt[e * T_TOK + pos];
        }
    } else {
        g_ctok[NROWS_ROUTED + pos] = pos;
        g_cwgt[NROWS_ROUTED + pos] = 1.f;
    }
}

// ---------------- batched transpose+cvt: [K][N] f32 -> [N][K] fp16 ------------
__device__ __forceinline__ void transpose_tile(
    const float* __restrict__ src, __half* __restrict__ dst, int K, int N,
    int n0, int k0, int tx, int ty)
{
    __shared__ float t[32][33];
#pragma unroll
    for (int i = 0; i < 32; i += 8)
        t[ty + i][tx] = src[(size_t)(k0 + ty + i) * N + n0 + tx];
    __syncthreads();
#pragma unroll
    for (int i = 0; i < 32; i += 8)
        dst[(size_t)(n0 + ty + i) * K + k0 + tx] = __float2half_rn(t[tx][ty + i]);
}

__global__ void cvt_gu_w_kernel(const float* __restrict__ gate_w,
                                const float* __restrict__ up_w,
                                const float* __restrict__ sg_w,
                                const float* __restrict__ su_w)
{
    const int z = blockIdx.z;
    const float* src; __half* dst;
    if (z < 8)       { src = gate_w + (size_t)z * HDIM * IDIM;        dst = g_gWt + (size_t)z * IDIM * HDIM; }
    else if (z < 16) { src = up_w   + (size_t)(z - 8) * HDIM * IDIM;  dst = g_uWt + (size_t)(z - 8) * IDIM * HDIM; }
    else if (z == 16){ src = sg_w;  dst = g_sgWt; }
    else             { src = su_w;  dst = g_suWt; }
    transpose_tile(src, dst, HDIM, IDIM, blockIdx.x * 32, blockIdx.y * 32,
                   threadIdx.x, threadIdx.y);
}
__global__ void cvt_dn_w_kernel(const float* __restrict__ down_w,
                                const float* __restrict__ sd_w)
{
    const int z = blockIdx.z;
    const float* src; __half* dst;
    if (z < 8) { src = down_w + (size_t)z * IDIM * HDIM; dst = g_dWt + (size_t)z * HDIM * IDIM; }
    else       { src = sd_w;  dst = g_sdWt; }
    transpose_tile(src, dst, IDIM, HDIM, blockIdx.x * 32, blockIdx.y * 32,
                   threadIdx.x, threadIdx.y);
}

// ============================================================================
// fp16 fused gate+up+act GEMM. 512 thr (16 warps, 4m x 4n), block 128x128,
// warp 32x32 each. K-tile 64, 3-stage cp.async pipeline, one barrier per kt.
// ============================================================================
#define PADH 72
#define TILE_H (128 * PADH)
#define NSTG 3
#define GU_SMEMB (NSTG * 3 * TILE_H * 2)   // 165888 B
#define DN_SMEMB (NSTG * 2 * TILE_H * 2)   // 110592 B

__global__ void __launch_bounds__(512, 1) gemm_gu_f16(void)
{
    const int e = blockIdx.z;
    const int n_e = (e < NEXP) ? g_count[e] : T_TOK;
    const int m0 = blockIdx.y * 128;
    if (m0 >= n_e) return;
    const int base = g_rowbase[e];
    const __half* __restrict__ Bg = (e < NEXP) ? (g_gWt + (size_t)e * IDIM * HDIM) : g_sgWt;
    const __half* __restrict__ Bu = (e < NEXP) ? (g_uWt + (size_t)e * IDIM * HDIM) : g_suWt;
    const int n0 = blockIdx.x * 128;

    const int tid  = threadIdx.x;
    const int warp = tid >> 5, lane = tid & 31;
    const int gi = lane >> 2, tig = lane & 3;
    const int wm = (warp & 3) * 32, wn = (warp >> 2) * 32;

    extern __shared__ __half sh[];
    __half* As  = sh;
    __half* Bgs = sh + NSTG * TILE_H;
    __half* Bus = sh + 2 * NSTG * TILE_H;
    const uint32_t uA = (uint32_t)__cvta_generic_to_shared(As);
    const uint32_t uG = (uint32_t)__cvta_generic_to_shared(Bgs);
    const uint32_t uU = (uint32_t)__cvta_generic_to_shared(Bus);

    const int pr0 = tid >> 3, pch = tid & 7;
    const __half* arow0;
    const __half* arow1;
    {
        int t0 = (m0 + pr0 < n_e)      ? g_ctok[base + m0 + pr0]      : g_ctok[base];
        int t1 = (m0 + pr0 + 64 < n_e) ? g_ctok[base + m0 + pr0 + 64] : g_ctok[base];
        arow0 = g_Xh + (size_t)t0 * HDIM + pch * 8;
        arow1 = g_Xh + (size_t)t1 * HDIM + pch * 8;
    }
    const __half* bgrow = Bg + (size_t)(n0 + pr0) * HDIM + pch * 8;
    const __half* burow = Bu + (size_t)(n0 + pr0) * HDIM + pch * 8;
    const size_t BROW64 = (size_t)64 * HDIM;
    const uint32_t d0 = (uint32_t)(pr0 * PADH + pch * 8) * 2;
    const uint32_t d1 = d0 + (uint32_t)(64 * PADH) * 2;

    float dg[2][4][4], du[2][4][4];
#pragma unroll
    for (int i = 0; i < 2; i++)
#pragma unroll
        for (int j = 0; j < 4; j++)
#pragma unroll
            for (int c = 0; c < 4; c++) { dg[i][j][c] = 0.f; du[i][j][c] = 0.f; }

    auto issue = [&](int kt, int s) {
        const int ko = kt * 64;
        const uint32_t bo = (uint32_t)(s * TILE_H * 2);
        cp_async16(uA + bo + d0, arow0 + ko);
        cp_async16(uA + bo + d1, arow1 + ko);
        cp_async16(uG + bo + d0, bgrow + ko);
        cp_async16(uG + bo + d1, bgrow + BROW64 + ko);
        cp_async16(uU + bo + d0, burow + ko);
        cp_async16(uU + bo + d1, burow + BROW64 + ko);
        cp_commit();
    };

    const int NK = HDIM / 64;   // 16
    issue(0, 0);
    issue(1, 1);
    int sbuf = 0;
    for (int kt = 0; kt < NK; kt++) {
        if (kt + 1 < NK) cp_wait<1>(); else cp_wait<0>();
        __syncthreads();
        if (kt + 2 < NK) {
            int s2 = sbuf + 2; if (s2 >= NSTG) s2 -= NSTG;
            issue(kt + 2, s2);
        }
        const __half* Ab = As  + sbuf * TILE_H;
        const __half* Gb = Bgs + sbuf * TILE_H;
        const __half* Ub = Bus + sbuf * TILE_H;
#pragma unroll
        for (int ks = 0; ks < 4; ks++) {
            const int kc = ks * 16 + 2 * tig;
            uint32_t af[2][4];
#pragma unroll
            for (int ms = 0; ms < 2; ms++) {
                const int mB = wm + ms * 16;
                af[ms][0] = *(const uint32_t*)&Ab[(mB + gi)     * PADH + kc];
                af[ms][1] = *(const uint32_t*)&Ab[(mB + 8 + gi) * PADH + kc];
                af[ms][2] = *(const uint32_t*)&Ab[(mB + gi)     * PADH + kc + 8];
                af[ms][3] = *(const uint32_t*)&Ab[(mB + 8 + gi) * PADH + kc + 8];
            }
            uint32_t bf[4][2];
#pragma unroll
            for (int ns = 0; ns < 4; ns++) {
                const int nB = wn + ns * 8 + gi;
                bf[ns][0] = *(const uint32_t*)&Gb[nB * PADH + kc];
                bf[ns][1] = *(const uint32_t*)&Gb[nB * PADH + kc + 8];
            }
#pragma unroll
            for (int ms = 0; ms < 2; ms++)
#pragma unroll
                for (int ns = 0; ns < 4; ns++)
                    mma_f16(dg[ms][ns], af[ms], bf[ns]);
#pragma unroll
            for (int ns = 0; ns < 4; ns++) {
                const int nB = wn + ns * 8 + gi;
                bf[ns][0] = *(const uint32_t*)&Ub[nB * PADH + kc];
                bf[ns][1] = *(const uint32_t*)&Ub[nB * PADH + kc + 8];
            }
#pragma unroll
            for (int ms = 0; ms < 2; ms++)
#pragma unroll
                for (int ns = 0; ns < 4; ns++)
                    mma_f16(du[ms][ns], af[ms], bf[ns]);
        }
        if (++sbuf == NSTG) sbuf = 0;
    }

#pragma unroll
    for (int ms = 0; ms < 2; ms++) {
#pragma unroll
        for (int hh = 0; hh < 2; hh++) {
            const int r = m0 + wm + ms * 16 + hh * 8 + gi;
            if (r < n_e) {
                const int row = base + r;
                const float w = g_cwgt[row];
                __half* C = g_Gh + (size_t)row * IDIM + n0 + wn;
#pragma unroll
                for (int ns = 0; ns < 4; ns++) {
                    float g0 = dg[ms][ns][2 * hh],     g1 = dg[ms][ns][2 * hh + 1];
                    float u0 = du[ms][ns][2 * hh],     u1 = du[ms][ns][2 * hh + 1];
                    float h0 = w * u0 * g0 / (1.f + __expf(-g0));
                    float h1 = w * u1 * g1 / (1.f + __expf(-g1));
                    *(__half2*)(C + ns * 8 + 2 * tig) = __floats2half2_rn(h0, h1);
                }
            }
        }
    }
}

// ============================================================================
// fp16 down GEMM + scatter. 256 thr (8 warps, 4m x 2n), warp 32x64,
// 2 CTAs/SM. K-tile 64, 3-stage pipeline, one barrier per kt.
// ============================================================================
__global__ void __launch_bounds__(256, 2) gemm_down_f16(float* __restrict__ out)
{
    const int e = blockIdx.z;
    const int n_e = (e < NEXP) ? g_count[e] : T_TOK;
    const int m0 = blockIdx.y * 128;
    if (m0 >= n_e) return;
    const int base = g_rowbase[e];
    const __half* __restrict__ B = (e < NEXP) ? (g_dWt + (size_t)e * HDIM * IDIM) : g_sdWt;
    const int n0 = blockIdx.x * 128;

    const int tid  = threadIdx.x;
    const int warp = tid >> 5, lane = tid & 31;
    const int gi = lane >> 2, tig = lane & 3;
    const int wm = (warp & 3) * 32, wn = (warp >> 2) * 64;

    extern __shared__ __half sh[];
    __half* As = sh;
    __half* Bs = sh + NSTG * TILE_H;
    const uint32_t uA = (uint32_t)__cvta_generic_to_shared(As);
    const uint32_t uB = (uint32_t)__cvta_generic_to_shared(Bs);

    const int pr0 = tid >> 3, pch = tid & 7;
    const __half* arow = g_Gh + (size_t)(base + m0 + pr0) * IDIM + pch * 8;
    const __half* brow = B + (size_t)(n0 + pr0) * IDIM + pch * 8;
    const size_t ROW32 = (size_t)32 * IDIM;
    const uint32_t ds0 = (uint32_t)(pr0 * PADH + pch * 8) * 2;
    const uint32_t SROW32 = (uint32_t)(32 * PADH) * 2;

    float d[2][8][4];
#pragma unroll
    for (int i = 0; i < 2; i++)
#pragma unroll
        for (int j = 0; j < 8; j++)
#pragma unroll
            for (int c = 0; c < 4; c++) d[i][j][c] = 0.f;

    auto issue = [&](int kt, int s) {
        const int ko = kt * 64;
        const uint32_t bo = (uint32_t)(s * TILE_H * 2);
#pragma unroll
        for (int c = 0; c < 4; c++) {
            cp_async16(uA + bo + ds0 + c * SROW32, arow + c * ROW32 + ko);
            cp_async16(uB + bo + ds0 + c * SROW32, brow + c * ROW32 + ko);
        }
        cp_commit();
    };

    const int NK = IDIM / 64;   // 32
    issue(0, 0);
    issue(1, 1);
    int sbuf = 0;
    for (int kt = 0; kt < NK; kt++) {
        if (kt + 1 < NK) cp_wait<1>(); else cp_wait<0>();
        __syncthreads();
        if (kt + 2 < NK) {
            int s2 = sbuf + 2; if (s2 >= NSTG) s2 -= NSTG;
            issue(kt + 2, s2);
        }
        const __half* Ab = As + sbuf * TILE_H;
        const __half* Bb = Bs + sbuf * TILE_H;
#pragma unroll
        for (int ks = 0; ks < 4; ks++) {
            const int kc = ks * 16 + 2 * tig;
            uint32_t af[2][4];
#pragma unroll
            for (int ms = 0; ms < 2; ms++) {
                const int mB = wm + ms * 16;
                af[ms][0] = *(const uint32_t*)&Ab[(mB + gi)     * PADH + kc];
                af[ms][1] = *(const uint32_t*)&Ab[(mB + 8 + gi) * PADH + kc];
                af[ms][2] = *(const uint32_t*)&Ab[(mB + gi)     * PADH + kc + 8];
                af[ms][3] = *(const uint32_t*)&Ab[(mB + 8 + gi) * PADH + kc + 8];
            }
            uint32_t bf[8][2];
#pragma unroll
            for (int ns = 0; ns < 8; ns++) {
                const int nB = wn + ns * 8 + gi;
                bf[ns][0] = *(const uint32_t*)&Bb[nB * PADH + kc];
                bf[ns][1] = *(const uint32_t*)&Bb[nB * PADH + kc + 8];
            }
#pragma unroll
            for (int ms = 0; ms < 2; ms++)
#pragma unroll
                for (int ns = 0; ns < 8; ns++)
                    mma_f16(d[ms][ns], af[ms], bf[ns]);
        }
        if (++sbuf == NSTG) sbuf = 0;
    }

#pragma unroll
    for (int ms = 0; ms < 2; ms++) {
        const int r0 = m0 + wm + ms * 16 + gi;
        const int r1 = r0 + 8;
        if (r0 < n_e) {
            const int tok = g_ctok[base + r0];
            float* o = out + (size_t)tok * HDIM + n0 + wn;
#pragma unroll
            for (int ns = 0; ns < 8; ns++) {
                atomicAdd(o + ns * 8 + 2 * tig,     d[ms][ns][0]);
                atomicAdd(o + ns * 8 + 2 * tig + 1, d[ms][ns][1]);
            }
        }
        if (r1 < n_e) {
            const int tok = g_ctok[base + r1];
            float* o = out + (size_t)tok * HDIM + n0 + wn;
#pragma unroll
            for (int ns = 0; ns < 8; ns++) {
                atomicAdd(o + ns * 8 + 2 * tig,     d[ms][ns][2]);
                atomicAdd(o + ns * 8 + 2 * tig + 1, d[ms][ns][3]);
            }
        }
    }
}

// ---------------- host launcher ----------------------------------------------
extern "C" void kernel_launch(void* const* d_in, const int* in_sizes, int n_in,
                              void* d_out, int out_size)
{
    const float* x       = (const float*)d_in[0];
    const float* rw      = (const float*)d_in[1];
    const float* gate_w  = (const float*)d_in[2];
    const float* up_w    = (const float*)d_in[3];
    const float* down_w  = (const float*)d_in[4];
    const float* sgate_w = (const float*)d_in[5];
    const float* sup_w   = (const float*)d_in[6];
    const float* sdown_w = (const float*)d_in[7];
    float* out = (float*)d_out;

    // one-time host-side objects (no device memory allocation)
    static cudaStream_t s1 = nullptr;
    static cudaEvent_t evFork = nullptr, evJoinGu = nullptr;
    static bool init_tried = false;
    if (!init_tried) {
        init_tried = true;
        if (cudaStreamCreateWithFlags(&s1, cudaStreamNonBlocking) != cudaSuccess) s1 = nullptr;
        if (s1) {
            if (cudaEventCreateWithFlags(&evFork,   cudaEventDisableTiming) != cudaSuccess ||
                cudaEventCreateWithFlags(&evJoinGu, cudaEventDisableTiming) != cudaSuccess)
                s1 = nullptr;
        }
    }

    void* cnt_addr = nullptr;
    cudaGetSymbolAddress(&cnt_addr, g_count);

    cudaFuncSetAttribute(gemm_gu_f16,
                         cudaFuncAttributeMaxDynamicSharedMemorySize, GU_SMEMB);
    cudaFuncSetAttribute(gemm_down_f16,
                         cudaFuncAttributeMaxDynamicSharedMemorySize, DN_SMEMB);

    dim3 tb(32, 8);
    dim3 grid_gu(IDIM / 128, T_TOK / 128, NEXP + 1);
    dim3 grid_dn(HDIM / 128, T_TOK / 128, NEXP + 1);

    if (s1) {
        // side stream: ONLY cvt_gu, overlapping the router chain. Nothing
        // ever overlaps the tensor-saturated GEMMs (R11 lesson).
        cudaEventRecord(evFork, 0);
        cudaStreamWaitEvent(s1, evFork, 0);
        cvt_gu_w_kernel<<<dim3(IDIM / 32, HDIM / 32, 18), tb, 0, s1>>>(
            gate_w, up_w, sgate_w, sup_w);
        cudaEventRecord(evJoinGu, s1);

        // main stream: routing chain (overlaps with cvt_gu), then cvt_dn
        // serially, then the GEMMs with the chip to themselves.
        cudaMemsetAsync(out, 0, (size_t)T_TOK * HDIM * sizeof(float));
        cudaMemsetAsync(cnt_addr, 0, NEXP * sizeof(int));
        router_kernel<<<ROUTER_BLOCKS, 256>>>(x, rw, out);
        finalize_kernel<<<1, 288>>>(out);
        compact_kernel<<<((NEXP + 1) * T_TOK) / 256, 256>>>();
        cvt_dn_w_kernel<<<dim3(HDIM / 32, IDIM / 32, 9), tb>>>(down_w, sdown_w);

        cudaStreamWaitEvent(0, evJoinGu, 0);
        gemm_gu_f16<<<grid_gu, 512, GU_SMEMB>>>();
        gemm_down_f16<<<grid_dn, 256, DN_SMEMB>>>(out);
    } else {
        // fallback: single-stream (R10 schedule)
        cudaMemsetAsync(out, 0, (size_t)T_TOK * HDIM * sizeof(float));
        cudaMemsetAsync(cnt_addr, 0, NEXP * sizeof(int));
        router_kernel<<<ROUTER_BLOCKS, 256>>>(x, rw, out);
        finalize_kernel<<<1, 288>>>(out);
        compact_kernel<<<((NEXP + 1) * T_TOK) / 256, 256>>>();
        cvt_gu_w_kernel<<<dim3(IDIM / 32, HDIM / 32, 18), tb>>>(gate_w, up_w, sgate_w, sup_w);
        cvt_dn_w_kernel<<<dim3(HDIM / 32, IDIM / 32, 9),  tb>>>(down_w, sdown_w);
        gemm_gu_f16<<<grid_gu, 512, GU_SMEMB>>>();
        gemm_down_f16<<<grid_dn, 256, DN_SMEMB>>>(out);
    }
}

// round 13
// speedup vs baseline: 1.0306x; 1.0061x over previous
#include <cuda_runtime.h>
#include <cuda_fp16.h>
#include <cstdint>
#include <cstddef>

// Problem constants
#define T_TOK   4096
#define HDIM    1024
#define IDIM    2048
#define NEXP    8
#define TOPK    2
#define NROWS_ROUTED (T_TOK * TOPK)         // 8192
#define NROWS_TOTAL  (NROWS_ROUTED + T_TOK) // 12288
#define ROUTER_BLOCKS (T_TOK / 8)           // 512

#define OUT_AUX    (T_TOK * HDIM)
#define OUT_Z      (OUT_AUX + 1)
#define OUT_LOGITS (OUT_AUX + 2)

// ---------------- scratch ----------------------------------------------------
__device__ int   g_count[NEXP];
__device__ int   g_list[NEXP * T_TOK];
__device__ float g_wgt [NEXP * T_TOK];
__device__ int   g_rowbase[NEXP + 1];
__device__ int   g_ctok[NROWS_TOTAL];
__device__ float g_cwgt[NROWS_TOTAL];
__device__ float g_pp[ROUTER_BLOCKS * NEXP];
__device__ float g_pl[ROUTER_BLOCKS];

// fp16 operands (16B-aligned for cp.async)
__device__ __align__(16) __half g_Xh [(size_t)T_TOK * HDIM];
__device__ __align__(16) __half g_Gh [(size_t)NROWS_TOTAL * IDIM];
__device__ __align__(16) __half g_gWt[(size_t)NEXP * IDIM * HDIM];  // [e][N][K]
__device__ __align__(16) __half g_uWt[(size_t)NEXP * IDIM * HDIM];
__device__ __align__(16) __half g_dWt[(size_t)NEXP * HDIM * IDIM];
__device__ __align__(16) __half g_sgWt[(size_t)IDIM * HDIM];
__device__ __align__(16) __half g_suWt[(size_t)IDIM * HDIM];
__device__ __align__(16) __half g_sdWt[(size_t)HDIM * IDIM];

// ---------------- helpers -----------------------------------------------------
__device__ __forceinline__ void cp_async16(uint32_t s, const void* g) {
    asm volatile("cp.async.cg.shared.global [%0], [%1], 16;\n" :: "r"(s), "l"(g));
}
__device__ __forceinline__ void cp_commit() {
    asm volatile("cp.async.commit_group;\n");
}
template <int N>
__device__ __forceinline__ void cp_wait() {
    asm volatile("cp.async.wait_group %0;\n" :: "n"(N));
}
__device__ __forceinline__ void mma_f16(float* d, const uint32_t* a, const uint32_t* b) {
    asm volatile(
        "mma.sync.aligned.m16n8k16.row.col.f32.f16.f16.f32 "
        "{%0,%1,%2,%3},{%4,%5,%6,%7},{%8,%9},{%0,%1,%2,%3};"
        : "+f"(d[0]), "+f"(d[1]), "+f"(d[2]), "+f"(d[3])
        : "r"(a[0]), "r"(a[1]), "r"(a[2]), "r"(a[3]), "r"(b[0]), "r"(b[1]));
}
// vectorized fp32 reduction (sm_90+): one RED op per value pair
__device__ __forceinline__ void red_add_f32x2(float* addr, float a, float b) {
    asm volatile("red.global.add.v2.f32 [%0], {%1, %2};"
                 :: "l"(addr), "f"(a), "f"(b) : "memory");
}

// ---------------- router (+ fused X->fp16 conversion) -------------------------
__global__ void __launch_bounds__(256) router_kernel(
    const float* __restrict__ x, const float* __restrict__ rw,
    float* __restrict__ out)
{
    const int warp = threadIdx.x >> 5, lane = threadIdx.x & 31;
    const int t = blockIdx.x * 8 + warp;

    float acc[NEXP];
#pragma unroll
    for (int e = 0; e < NEXP; e++) acc[e] = 0.f;

    const float* xr = x + (size_t)t * HDIM;
    for (int h = lane; h < HDIM; h += 32) {
        float xv = xr[h];
        const float* r = rw + (size_t)h * NEXP;
#pragma unroll
        for (int e = 0; e < NEXP; e++) acc[e] += xv * r[e];
    }
    // fused fp16 conversion of this token's row (L2-hot)
    {
        __half2* dst = (__half2*)(g_Xh + (size_t)t * HDIM);
        for (int h = lane; h < HDIM / 2; h += 32) {
            float2 v = *(const float2*)(xr + 2 * h);
            dst[h] = __floats2half2_rn(v.x, v.y);
        }
    }
#pragma unroll
    for (int off = 16; off > 0; off >>= 1)
#pragma unroll
        for (int e = 0; e < NEXP; e++)
            acc[e] += __shfl_xor_sync(0xFFFFFFFFu, acc[e], off);

    __shared__ float s_prob[8][NEXP];
    __shared__ float s_lse2[8];

    if (lane == 0) {
        float mx = acc[0];
#pragma unroll
        for (int e = 1; e < NEXP; e++) mx = fmaxf(mx, acc[e]);
        float p[NEXP], sum = 0.f;
#pragma unroll
        for (int e = 0; e < NEXP; e++) { p[e] = expf(acc[e] - mx); sum += p[e]; }
        float lse = logf(sum) + mx;
        s_lse2[warp] = lse * lse;
        float inv = 1.f / sum;
#pragma unroll
        for (int e = 0; e < NEXP; e++) {
            p[e] *= inv;
            s_prob[warp][e] = p[e];
            out[OUT_LOGITS + (size_t)t * NEXP + e] = acc[e];
        }
        int i1 = 0;
#pragma unroll
        for (int e = 1; e < NEXP; e++) if (p[e] > p[i1]) i1 = e;
        int i2 = (i1 == 0) ? 1 : 0;
#pragma unroll
        for (int e = 0; e < NEXP; e++) if (e != i2 && e != i1 && p[e] > p[i2]) i2 = e;
        float s2 = p[i1] + p[i2];
        float w1 = p[i1] / s2, w2 = p[i2] / s2;
        int pos1 = atomicAdd(&g_count[i1], 1);
        g_list[i1 * T_TOK + pos1] = t; g_wgt[i1 * T_TOK + pos1] = w1;
        int pos2 = atomicAdd(&g_count[i2], 1);
        g_list[i2 * T_TOK + pos2] = t; g_wgt[i2 * T_TOK + pos2] = w2;
    }
    __syncthreads();
    if (threadIdx.x == 0) {
        float ps[NEXP]; float l2 = 0.f;
#pragma unroll
        for (int e = 0; e < NEXP; e++) ps[e] = 0.f;
        for (int w = 0; w < 8; w++) {
            l2 += s_lse2[w];
#pragma unroll
            for (int e = 0; e < NEXP; e++) ps[e] += s_prob[w][e];
        }
#pragma unroll
        for (int e = 0; e < NEXP; e++) g_pp[blockIdx.x * NEXP + e] = ps[e];
        g_pl[blockIdx.x] = l2;
    }
}

// ---------------- finalize ----------------------------------------------------
__global__ void finalize_kernel(float* __restrict__ out) {
    const int warp = threadIdx.x >> 5, lane = threadIdx.x & 31;
    __shared__ float red[NEXP + 1];
    if (warp < NEXP) {
        float s = 0.f;
        for (int j = 0; j < ROUTER_BLOCKS / 32; j++)
            s += g_pp[(size_t)(lane + 32 * j) * NEXP + warp];
#pragma unroll
        for (int off = 16; off > 0; off >>= 1) s += __shfl_xor_sync(0xFFFFFFFFu, s, off);
        if (lane == 0) red[warp] = s;
    } else if (warp == NEXP) {
        float s = 0.f;
        for (int j = 0; j < ROUTER_BLOCKS / 32; j++)
            s += g_pl[lane + 32 * j];
#pragma unroll
        for (int off = 16; off > 0; off >>= 1) s += __shfl_xor_sync(0xFFFFFFFFu, s, off);
        if (lane == 0) red[NEXP] = s;
    }
    __syncthreads();
    if (threadIdx.x == 0) {
        float aux = 0.f;
        int rb = 0;
        for (int e = 0; e < NEXP; e++) {
            aux += ((float)g_count[e] / (float)(T_TOK * TOPK)) * (red[e] / (float)T_TOK);
            g_rowbase[e] = rb;
            rb += g_count[e];
        }
        g_rowbase[NEXP] = NROWS_ROUTED;
        out[OUT_AUX] = (float)NEXP * aux;
        out[OUT_Z]   = red[NEXP] / (float)T_TOK;
    }
}

// ---------------- compact -----------------------------------------------------
__global__ void compact_kernel() {
    int idx = blockIdx.x * blockDim.x + threadIdx.x;
    int e = idx / T_TOK, pos = idx % T_TOK;
    if (e < NEXP) {
        if (pos < g_count[e]) {
            int cr = g_rowbase[e] + pos;
            g_ctok[cr] = g_list[e * T_TOK + pos];
            g_cwgt[cr] = g_wgt[e * T_TOK + pos];
        }
    } else {
        g_ctok[NROWS_ROUTED + pos] = pos;
        g_cwgt[NROWS_ROUTED + pos] = 1.f;
    }
}

// ---------------- batched transpose+cvt: [K][N] f32 -> [N][K] fp16 ------------
__device__ __forceinline__ void transpose_tile(
    const float* __restrict__ src, __half* __restrict__ dst, int K, int N,
    int n0, int k0, int tx, int ty)
{
    __shared__ float t[32][33];
#pragma unroll
    for (int i = 0; i < 32; i += 8)
        t[ty + i][tx] = src[(size_t)(k0 + ty + i) * N + n0 + tx];
    __syncthreads();
#pragma unroll
    for (int i = 0; i < 32; i += 8)
        dst[(size_t)(n0 + ty + i) * K + k0 + tx] = __float2half_rn(t[tx][ty + i]);
}

__global__ void cvt_gu_w_kernel(const float* __restrict__ gate_w,
                                const float* __restrict__ up_w,
                                const float* __restrict__ sg_w,
                                const float* __restrict__ su_w)
{
    const int z = blockIdx.z;
    const float* src; __half* dst;
    if (z < 8)       { src = gate_w + (size_t)z * HDIM * IDIM;        dst = g_gWt + (size_t)z * IDIM * HDIM; }
    else if (z < 16) { src = up_w   + (size_t)(z - 8) * HDIM * IDIM;  dst = g_uWt + (size_t)(z - 8) * IDIM * HDIM; }
    else if (z == 16){ src = sg_w;  dst = g_sgWt; }
    else             { src = su_w;  dst = g_suWt; }
    transpose_tile(src, dst, HDIM, IDIM, blockIdx.x * 32, blockIdx.y * 32,
                   threadIdx.x, threadIdx.y);
}
__global__ void cvt_dn_w_kernel(const float* __restrict__ down_w,
                                const float* __restrict__ sd_w)
{
    const int z = blockIdx.z;
    const float* src; __half* dst;
    if (z < 8) { src = down_w + (size_t)z * IDIM * HDIM; dst = g_dWt + (size_t)z * HDIM * IDIM; }
    else       { src = sd_w;  dst = g_sdWt; }
    transpose_tile(src, dst, IDIM, HDIM, blockIdx.x * 32, blockIdx.y * 32,
                   threadIdx.x, threadIdx.y);
}

// ============================================================================
// fp16 fused gate+up+act GEMM. 512 thr (16 warps, 4m x 4n), block 128x128,
// warp 32x32 each. K-tile 64, 3-stage cp.async pipeline, one barrier per kt.
// ============================================================================
#define PADH 72
#define TILE_H (128 * PADH)
#define NSTG 3
#define GU_SMEMB (NSTG * 3 * TILE_H * 2)   // 165888 B
#define DN_SMEMB (NSTG * 2 * TILE_H * 2)   // 110592 B

__global__ void __launch_bounds__(512, 1) gemm_gu_f16(void)
{
    const int e = blockIdx.z;
    const int n_e = (e < NEXP) ? g_count[e] : T_TOK;
    const int m0 = blockIdx.y * 128;
    if (m0 >= n_e) return;
    const int base = g_rowbase[e];
    const __half* __restrict__ Bg = (e < NEXP) ? (g_gWt + (size_t)e * IDIM * HDIM) : g_sgWt;
    const __half* __restrict__ Bu = (e < NEXP) ? (g_uWt + (size_t)e * IDIM * HDIM) : g_suWt;
    const int n0 = blockIdx.x * 128;

    const int tid  = threadIdx.x;
    const int warp = tid >> 5, lane = tid & 31;
    const int gi = lane >> 2, tig = lane & 3;
    const int wm = (warp & 3) * 32, wn = (warp >> 2) * 32;

    extern __shared__ __half sh[];
    __half* As  = sh;
    __half* Bgs = sh + NSTG * TILE_H;
    __half* Bus = sh + 2 * NSTG * TILE_H;
    const uint32_t uA = (uint32_t)__cvta_generic_to_shared(As);
    const uint32_t uG = (uint32_t)__cvta_generic_to_shared(Bgs);
    const uint32_t uU = (uint32_t)__cvta_generic_to_shared(Bus);

    const int pr0 = tid >> 3, pch = tid & 7;
    const __half* arow0;
    const __half* arow1;
    {
        int t0 = (m0 + pr0 < n_e)      ? g_ctok[base + m0 + pr0]      : g_ctok[base];
        int t1 = (m0 + pr0 + 64 < n_e) ? g_ctok[base + m0 + pr0 + 64] : g_ctok[base];
        arow0 = g_Xh + (size_t)t0 * HDIM + pch * 8;
        arow1 = g_Xh + (size_t)t1 * HDIM + pch * 8;
    }
    const __half* bgrow = Bg + (size_t)(n0 + pr0) * HDIM + pch * 8;
    const __half* burow = Bu + (size_t)(n0 + pr0) * HDIM + pch * 8;
    const size_t BROW64 = (size_t)64 * HDIM;
    const uint32_t d0 = (uint32_t)(pr0 * PADH + pch * 8) * 2;
    const uint32_t d1 = d0 + (uint32_t)(64 * PADH) * 2;

    float dg[2][4][4], du[2][4][4];
#pragma unroll
    for (int i = 0; i < 2; i++)
#pragma unroll
        for (int j = 0; j < 4; j++)
#pragma unroll
            for (int c = 0; c < 4; c++) { dg[i][j][c] = 0.f; du[i][j][c] = 0.f; }

    auto issue = [&](int kt, int s) {
        const int ko = kt * 64;
        const uint32_t bo = (uint32_t)(s * TILE_H * 2);
        cp_async16(uA + bo + d0, arow0 + ko);
        cp_async16(uA + bo + d1, arow1 + ko);
        cp_async16(uG + bo + d0, bgrow + ko);
        cp_async16(uG + bo + d1, bgrow + BROW64 + ko);
        cp_async16(uU + bo + d0, burow + ko);
        cp_async16(uU + bo + d1, burow + BROW64 + ko);
        cp_commit();
    };

    const int NK = HDIM / 64;   // 16
    issue(0, 0);
    issue(1, 1);
    int sbuf = 0;
    for (int kt = 0; kt < NK; kt++) {
        if (kt + 1 < NK) cp_wait<1>(); else cp_wait<0>();
        __syncthreads();
        if (kt + 2 < NK) {
            int s2 = sbuf + 2; if (s2 >= NSTG) s2 -= NSTG;
            issue(kt + 2, s2);
        }
        const __half* Ab = As  + sbuf * TILE_H;
        const __half* Gb = Bgs + sbuf * TILE_H;
        const __half* Ub = Bus + sbuf * TILE_H;
#pragma unroll
        for (int ks = 0; ks < 4; ks++) {
            const int kc = ks * 16 + 2 * tig;
            uint32_t af[2][4];
#pragma unroll
            for (int ms = 0; ms < 2; ms++) {
                const int mB = wm + ms * 16;
                af[ms][0] = *(const uint32_t*)&Ab[(mB + gi)     * PADH + kc];
                af[ms][1] = *(const uint32_t*)&Ab[(mB + 8 + gi) * PADH + kc];
                af[ms][2] = *(const uint32_t*)&Ab[(mB + gi)     * PADH + kc + 8];
                af[ms][3] = *(const uint32_t*)&Ab[(mB + 8 + gi) * PADH + kc + 8];
            }
            uint32_t bf[4][2];
#pragma unroll
            for (int ns = 0; ns < 4; ns++) {
                const int nB = wn + ns * 8 + gi;
                bf[ns][0] = *(const uint32_t*)&Gb[nB * PADH + kc];
                bf[ns][1] = *(const uint32_t*)&Gb[nB * PADH + kc + 8];
            }
#pragma unroll
            for (int ms = 0; ms < 2; ms++)
#pragma unroll
                for (int ns = 0; ns < 4; ns++)
                    mma_f16(dg[ms][ns], af[ms], bf[ns]);
#pragma unroll
            for (int ns = 0; ns < 4; ns++) {
                const int nB = wn + ns * 8 + gi;
                bf[ns][0] = *(const uint32_t*)&Ub[nB * PADH + kc];
                bf[ns][1] = *(const uint32_t*)&Ub[nB * PADH + kc + 8];
            }
#pragma unroll
            for (int ms = 0; ms < 2; ms++)
#pragma unroll
                for (int ns = 0; ns < 4; ns++)
                    mma_f16(du[ms][ns], af[ms], bf[ns]);
        }
        if (++sbuf == NSTG) sbuf = 0;
    }

#pragma unroll
    for (int ms = 0; ms < 2; ms++) {
#pragma unroll
        for (int hh = 0; hh < 2; hh++) {
            const int r = m0 + wm + ms * 16 + hh * 8 + gi;
            if (r < n_e) {
                const int row = base + r;
                const float w = g_cwgt[row];
                __half* C = g_Gh + (size_t)row * IDIM + n0 + wn;
#pragma unroll
                for (int ns = 0; ns < 4; ns++) {
                    float g0 = dg[ms][ns][2 * hh],     g1 = dg[ms][ns][2 * hh + 1];
                    float u0 = du[ms][ns][2 * hh],     u1 = du[ms][ns][2 * hh + 1];
                    float h0 = w * u0 * g0 / (1.f + __expf(-g0));
                    float h1 = w * u1 * g1 / (1.f + __expf(-g1));
                    *(__half2*)(C + ns * 8 + 2 * tig) = __floats2half2_rn(h0, h1);
                }
            }
        }
    }
}

// ============================================================================
// fp16 down GEMM + scatter. 256 thr (8 warps, 4m x 2n), warp 32x64,
// 2 CTAs/SM. K-tile 64, 3-stage pipeline. Epilogue: vectorized red.v2.f32.
// ============================================================================
__global__ void __launch_bounds__(256, 2) gemm_down_f16(float* __restrict__ out)
{
    const int e = blockIdx.z;
    const int n_e = (e < NEXP) ? g_count[e] : T_TOK;
    const int m0 = blockIdx.y * 128;
    if (m0 >= n_e) return;
    const int base = g_rowbase[e];
    const __half* __restrict__ B = (e < NEXP) ? (g_dWt + (size_t)e * HDIM * IDIM) : g_sdWt;
    const int n0 = blockIdx.x * 128;

    const int tid  = threadIdx.x;
    const int warp = tid >> 5, lane = tid & 31;
    const int gi = lane >> 2, tig = lane & 3;
    const int wm = (warp & 3) * 32, wn = (warp >> 2) * 64;

    extern __shared__ __half sh[];
    __half* As = sh;
    __half* Bs = sh + NSTG * TILE_H;
    const uint32_t uA = (uint32_t)__cvta_generic_to_shared(As);
    const uint32_t uB = (uint32_t)__cvta_generic_to_shared(Bs);

    const int pr0 = tid >> 3, pch = tid & 7;
    const __half* arow = g_Gh + (size_t)(base + m0 + pr0) * IDIM + pch * 8;
    const __half* brow = B + (size_t)(n0 + pr0) * IDIM + pch * 8;
    const size_t ROW32 = (size_t)32 * IDIM;
    const uint32_t ds0 = (uint32_t)(pr0 * PADH + pch * 8) * 2;
    const uint32_t SROW32 = (uint32_t)(32 * PADH) * 2;

    float d[2][8][4];
#pragma unroll
    for (int i = 0; i < 2; i++)
#pragma unroll
        for (int j = 0; j < 8; j++)
#pragma unroll
            for (int c = 0; c < 4; c++) d[i][j][c] = 0.f;

    auto issue = [&](int kt, int s) {
        const int ko = kt * 64;
        const uint32_t bo = (uint32_t)(s * TILE_H * 2);
#pragma unroll
        for (int c = 0; c < 4; c++) {
            cp_async16(uA + bo + ds0 + c * SROW32, arow + c * ROW32 + ko);
            cp_async16(uB + bo + ds0 + c * SROW32, brow + c * ROW32 + ko);
        }
        cp_commit();
    };

    const int NK = IDIM / 64;   // 32
    issue(0, 0);
    issue(1, 1);
    int sbuf = 0;
    for (int kt = 0; kt < NK; kt++) {
        if (kt + 1 < NK) cp_wait<1>(); else cp_wait<0>();
        __syncthreads();
        if (kt + 2 < NK) {
            int s2 = sbuf + 2; if (s2 >= NSTG) s2 -= NSTG;
            issue(kt + 2, s2);
        }
        const __half* Ab = As + sbuf * TILE_H;
        const __half* Bb = Bs + sbuf * TILE_H;
#pragma unroll
        for (int ks = 0; ks < 4; ks++) {
            const int kc = ks * 16 + 2 * tig;
            uint32_t af[2][4];
#pragma unroll
            for (int ms = 0; ms < 2; ms++) {
                const int mB = wm + ms * 16;
                af[ms][0] = *(const uint32_t*)&Ab[(mB + gi)     * PADH + kc];
                af[ms][1] = *(const uint32_t*)&Ab[(mB + 8 + gi) * PADH + kc];
                af[ms][2] = *(const uint32_t*)&Ab[(mB + gi)     * PADH + kc + 8];
                af[ms][3] = *(const uint32_t*)&Ab[(mB + 8 + gi) * PADH + kc + 8];
            }
            uint32_t bf[8][2];
#pragma unroll
            for (int ns = 0; ns < 8; ns++) {
                const int nB = wn + ns * 8 + gi;
                bf[ns][0] = *(const uint32_t*)&Bb[nB * PADH + kc];
                bf[ns][1] = *(const uint32_t*)&Bb[nB * PADH + kc + 8];
            }
#pragma unroll
            for (int ms = 0; ms < 2; ms++)
#pragma unroll
                for (int ns = 0; ns < 8; ns++)
                    mma_f16(d[ms][ns], af[ms], bf[ns]);
        }
        if (++sbuf == NSTG) sbuf = 0;
    }

    // epilogue: vectorized scatter-accumulate (red.v2.f32; 8B-aligned pairs)
#pragma unroll
    for (int ms = 0; ms < 2; ms++) {
        const int r0 = m0 + wm + ms * 16 + gi;
        const int r1 = r0 + 8;
        if (r0 < n_e) {
            const int tok = g_ctok[base + r0];
            float* o = out + (size_t)tok * HDIM + n0 + wn;
#pragma unroll
            for (int ns = 0; ns < 8; ns++)
                red_add_f32x2(o + ns * 8 + 2 * tig, d[ms][ns][0], d[ms][ns][1]);
        }
        if (r1 < n_e) {
            const int tok = g_ctok[base + r1];
            float* o = out + (size_t)tok * HDIM + n0 + wn;
#pragma unroll
            for (int ns = 0; ns < 8; ns++)
                red_add_f32x2(o + ns * 8 + 2 * tig, d[ms][ns][2], d[ms][ns][3]);
        }
    }
}

// ---------------- host launcher ----------------------------------------------
extern "C" void kernel_launch(void* const* d_in, const int* in_sizes, int n_in,
                              void* d_out, int out_size)
{
    const float* x       = (const float*)d_in[0];
    const float* rw      = (const float*)d_in[1];
    const float* gate_w  = (const float*)d_in[2];
    const float* up_w    = (const float*)d_in[3];
    const float* down_w  = (const float*)d_in[4];
    const float* sgate_w = (const float*)d_in[5];
    const float* sup_w   = (const float*)d_in[6];
    const float* sdown_w = (const float*)d_in[7];
    float* out = (float*)d_out;

    void* cnt_addr = nullptr;
    cudaGetSymbolAddress(&cnt_addr, g_count);

    cudaFuncSetAttribute(gemm_gu_f16,
                         cudaFuncAttributeMaxDynamicSharedMemorySize, GU_SMEMB);
    cudaFuncSetAttribute(gemm_down_f16,
                         cudaFuncAttributeMaxDynamicSharedMemorySize, DN_SMEMB);

    dim3 tb(32, 8);
    dim3 grid_gu(IDIM / 128, T_TOK / 128, NEXP + 1);
    dim3 grid_dn(HDIM / 128, T_TOK / 128, NEXP + 1);

    // single-stream schedule (R10 optimum): nothing overlaps the GEMMs
    cudaMemsetAsync(out, 0, (size_t)T_TOK * HDIM * sizeof(float));
    cudaMemsetAsync(cnt_addr, 0, NEXP * sizeof(int));
    router_kernel<<<ROUTER_BLOCKS, 256>>>(x, rw, out);
    finalize_kernel<<<1, 288>>>(out);
    compact_kernel<<<((NEXP + 1) * T_TOK) / 256, 256>>>();
    cvt_gu_w_kernel<<<dim3(IDIM / 32, HDIM / 32, 18), tb>>>(gate_w, up_w, sgate_w, sup_w);
    cvt_dn_w_kernel<<<dim3(HDIM / 32, IDIM / 32, 9),  tb>>>(down_w, sdown_w);
    gemm_gu_f16<<<grid_gu, 512, GU_SMEMB>>>();
    gemm_down_f16<<<grid_dn, 256, DN_SMEMB>>>(out);
}

// round 14
// speedup vs baseline: 1.0462x; 1.0151x over previous
#include <cuda_runtime.h>
#include <cuda_fp16.h>
#include <cstdint>
#include <cstddef>

// Problem constants
#define T_TOK   4096
#define HDIM    1024
#define IDIM    2048
#define NEXP    8
#define TOPK    2
#define NROWS_ROUTED (T_TOK * TOPK)         // 8192
#define NROWS_TOTAL  (NROWS_ROUTED + T_TOK) // 12288
#define ROUTER_BLOCKS (T_TOK / 8)           // 512

#define OUT_AUX    (T_TOK * HDIM)
#define OUT_Z      (OUT_AUX + 1)
#define OUT_LOGITS (OUT_AUX + 2)

// ---------------- scratch ----------------------------------------------------
__device__ int   g_count[NEXP];
__device__ int   g_list[NEXP * T_TOK];
__device__ float g_wgt [NEXP * T_TOK];
__device__ int   g_rowbase[NEXP + 1];
__device__ int   g_ctok[NROWS_TOTAL];
__device__ float g_cwgt[NROWS_TOTAL];
__device__ float g_pp[ROUTER_BLOCKS * NEXP];
__device__ float g_pl[ROUTER_BLOCKS];

// fp16 operands (16B-aligned for cp.async)
__device__ __align__(16) __half g_Xh [(size_t)T_TOK * HDIM];
__device__ __align__(16) __half g_Gh [(size_t)NROWS_TOTAL * IDIM];
__device__ __align__(16) __half g_gWt[(size_t)NEXP * IDIM * HDIM];  // [e][N][K]
__device__ __align__(16) __half g_uWt[(size_t)NEXP * IDIM * HDIM];
__device__ __align__(16) __half g_dWt[(size_t)NEXP * HDIM * IDIM];
__device__ __align__(16) __half g_sgWt[(size_t)IDIM * HDIM];
__device__ __align__(16) __half g_suWt[(size_t)IDIM * HDIM];
__device__ __align__(16) __half g_sdWt[(size_t)HDIM * IDIM];

// ---------------- helpers -----------------------------------------------------
__device__ __forceinline__ void cp_async16(uint32_t s, const void* g) {
    asm volatile("cp.async.cg.shared.global [%0], [%1], 16;\n" :: "r"(s), "l"(g));
}
__device__ __forceinline__ void cp_commit() {
    asm volatile("cp.async.commit_group;\n");
}
template <int N>
__device__ __forceinline__ void cp_wait() {
    asm volatile("cp.async.wait_group %0;\n" :: "n"(N));
}
__device__ __forceinline__ void mma_f16(float* d, const uint32_t* a, const uint32_t* b) {
    asm volatile(
        "mma.sync.aligned.m16n8k16.row.col.f32.f16.f16.f32 "
        "{%0,%1,%2,%3},{%4,%5,%6,%7},{%8,%9},{%0,%1,%2,%3};"
        : "+f"(d[0]), "+f"(d[1]), "+f"(d[2]), "+f"(d[3])
        : "r"(a[0]), "r"(a[1]), "r"(a[2]), "r"(a[3]), "r"(b[0]), "r"(b[1]));
}
// vectorized fp32 reduction (sm_90+): one RED op per value pair
__device__ __forceinline__ void red_add_f32x2(float* addr, float a, float b) {
    asm volatile("red.global.add.v2.f32 [%0], {%1, %2};"
                 :: "l"(addr), "f"(a), "f"(b) : "memory");
}

// ---------------- router (+ fused X->fp16 conversion) -------------------------
__global__ void __launch_bounds__(256) router_kernel(
    const float* __restrict__ x, const float* __restrict__ rw,
    float* __restrict__ out)
{
    const int warp = threadIdx.x >> 5, lane = threadIdx.x & 31;
    const int t = blockIdx.x * 8 + warp;

    float acc[NEXP];
#pragma unroll
    for (int e = 0; e < NEXP; e++) acc[e] = 0.f;

    const float* xr = x + (size_t)t * HDIM;
    for (int h = lane; h < HDIM; h += 32) {
        float xv = xr[h];
        const float* r = rw + (size_t)h * NEXP;
#pragma unroll
        for (int e = 0; e < NEXP; e++) acc[e] += xv * r[e];
    }
    // fused fp16 conversion of this token's row (L2-hot)
    {
        __half2* dst = (__half2*)(g_Xh + (size_t)t * HDIM);
        for (int h = lane; h < HDIM / 2; h += 32) {
            float2 v = *(const float2*)(xr + 2 * h);
            dst[h] = __floats2half2_rn(v.x, v.y);
        }
    }
#pragma unroll
    for (int off = 16; off > 0; off >>= 1)
#pragma unroll
        for (int e = 0; e < NEXP; e++)
            acc[e] += __shfl_xor_sync(0xFFFFFFFFu, acc[e], off);

    __shared__ float s_prob[8][NEXP];
    __shared__ float s_lse2[8];

    if (lane == 0) {
        float mx = acc[0];
#pragma unroll
        for (int e = 1; e < NEXP; e++) mx = fmaxf(mx, acc[e]);
        float p[NEXP], sum = 0.f;
#pragma unroll
        for (int e = 0; e < NEXP; e++) { p[e] = expf(acc[e] - mx); sum += p[e]; }
        float lse = logf(sum) + mx;
        s_lse2[warp] = lse * lse;
        float inv = 1.f / sum;
#pragma unroll
        for (int e = 0; e < NEXP; e++) {
            p[e] *= inv;
            s_prob[warp][e] = p[e];
            out[OUT_LOGITS + (size_t)t * NEXP + e] = acc[e];
        }
        int i1 = 0;
#pragma unroll
        for (int e = 1; e < NEXP; e++) if (p[e] > p[i1]) i1 = e;
        int i2 = (i1 == 0) ? 1 : 0;
#pragma unroll
        for (int e = 0; e < NEXP; e++) if (e != i2 && e != i1 && p[e] > p[i2]) i2 = e;
        float s2 = p[i1] + p[i2];
        float w1 = p[i1] / s2, w2 = p[i2] / s2;
        int pos1 = atomicAdd(&g_count[i1], 1);
        g_list[i1 * T_TOK + pos1] = t; g_wgt[i1 * T_TOK + pos1] = w1;
        int pos2 = atomicAdd(&g_count[i2], 1);
        g_list[i2 * T_TOK + pos2] = t; g_wgt[i2 * T_TOK + pos2] = w2;
    }
    __syncthreads();
    if (threadIdx.x == 0) {
        float ps[NEXP]; float l2 = 0.f;
#pragma unroll
        for (int e = 0; e < NEXP; e++) ps[e] = 0.f;
        for (int w = 0; w < 8; w++) {
            l2 += s_lse2[w];
#pragma unroll
            for (int e = 0; e < NEXP; e++) ps[e] += s_prob[w][e];
        }
#pragma unroll
        for (int e = 0; e < NEXP; e++) g_pp[blockIdx.x * NEXP + e] = ps[e];
        g_pl[blockIdx.x] = l2;
    }
}

// ---------------- finalize ----------------------------------------------------
__global__ void finalize_kernel(float* __restrict__ out) {
    const int warp = threadIdx.x >> 5, lane = threadIdx.x & 31;
    __shared__ float red[NEXP + 1];
    if (warp < NEXP) {
        float s = 0.f;
        for (int j = 0; j < ROUTER_BLOCKS / 32; j++)
            s += g_pp[(size_t)(lane + 32 * j) * NEXP + warp];
#pragma unroll
        for (int off = 16; off > 0; off >>= 1) s += __shfl_xor_sync(0xFFFFFFFFu, s, off);
        if (lane == 0) red[warp] = s;
    } else if (warp == NEXP) {
        float s = 0.f;
        for (int j = 0; j < ROUTER_BLOCKS / 32; j++)
            s += g_pl[lane + 32 * j];
#pragma unroll
        for (int off = 16; off > 0; off >>= 1) s += __shfl_xor_sync(0xFFFFFFFFu, s, off);
        if (lane == 0) red[NEXP] = s;
    }
    __syncthreads();
    if (threadIdx.x == 0) {
        float aux = 0.f;
        int rb = 0;
        for (int e = 0; e < NEXP; e++) {
            aux += ((float)g_count[e] / (float)(T_TOK * TOPK)) * (red[e] / (float)T_TOK);
            g_rowbase[e] = rb;
            rb += g_count[e];
        }
        g_rowbase[NEXP] = NROWS_ROUTED;
        out[OUT_AUX] = (float)NEXP * aux;
        out[OUT_Z]   = red[NEXP] / (float)T_TOK;
    }
}

// ---------------- compact -----------------------------------------------------
__global__ void compact_kernel() {
    int idx = blockIdx.x * blockDim.x + threadIdx.x;
    int e = idx / T_TOK, pos = idx % T_TOK;
    if (e < NEXP) {
        if (pos < g_count[e]) {
            int cr = g_rowbase[e] + pos;
            g_ctok[cr] = g_list[e * T_TOK + pos];
            g_cwgt[cr] = g_wgt[e * T_TOK + pos];
        }
    } else {
        g_ctok[NROWS_ROUTED + pos] = pos;
        g_cwgt[NROWS_ROUTED + pos] = 1.f;
    }
}

// ---------------- batched transpose+cvt: [K][N] f32 -> [N][K] fp16 ------------
// 64-K x 32-N tile: reads 128B fp32 rows, writes 128B fp16 rows (half2/thread).
__device__ __forceinline__ void transpose_tile64(
    const float* __restrict__ src, __half* __restrict__ dst, int K, int N,
    int n0, int k0, int tx, int ty)
{
    __shared__ float t[64][33];
#pragma unroll
    for (int i = 0; i < 64; i += 8)
        t[ty + i][tx] = src[(size_t)(k0 + ty + i) * N + n0 + tx];
    __syncthreads();
#pragma unroll
    for (int i = 0; i < 32; i += 8) {
        float a = t[2 * tx][ty + i];
        float b = t[2 * tx + 1][ty + i];
        *(__half2*)&dst[(size_t)(n0 + ty + i) * K + k0 + 2 * tx] =
            __floats2half2_rn(a, b);
    }
}

__global__ void cvt_gu_w_kernel(const float* __restrict__ gate_w,
                                const float* __restrict__ up_w,
                                const float* __restrict__ sg_w,
                                const float* __restrict__ su_w)
{
    const int z = blockIdx.z;
    const float* src; __half* dst;
    if (z < 8)       { src = gate_w + (size_t)z * HDIM * IDIM;        dst = g_gWt + (size_t)z * IDIM * HDIM; }
    else if (z < 16) { src = up_w   + (size_t)(z - 8) * HDIM * IDIM;  dst = g_uWt + (size_t)(z - 8) * IDIM * HDIM; }
    else if (z == 16){ src = sg_w;  dst = g_sgWt; }
    else             { src = su_w;  dst = g_suWt; }
    transpose_tile64(src, dst, HDIM, IDIM, blockIdx.x * 32, blockIdx.y * 64,
                     threadIdx.x, threadIdx.y);
}
__global__ void cvt_dn_w_kernel(const float* __restrict__ down_w,
                                const float* __restrict__ sd_w)
{
    const int z = blockIdx.z;
    const float* src; __half* dst;
    if (z < 8) { src = down_w + (size_t)z * IDIM * HDIM; dst = g_dWt + (size_t)z * HDIM * IDIM; }
    else       { src = sd_w;  dst = g_sdWt; }
    transpose_tile64(src, dst, IDIM, HDIM, blockIdx.x * 32, blockIdx.y * 64,
                     threadIdx.x, threadIdx.y);
}

// ============================================================================
// fp16 fused gate+up+act GEMM. 512 thr (16 warps, 4m x 4n), block 128x128,
// warp 32x32 each. K-tile 64, 3-stage cp.async pipeline, one barrier per kt.
// ============================================================================
#define PADH 72
#define TILE_H (128 * PADH)
#define NSTG 3
#define GU_SMEMB (NSTG * 3 * TILE_H * 2)   // 165888 B
#define DN_SMEMB (NSTG * 2 * TILE_H * 2)   // 110592 B

__global__ void __launch_bounds__(512, 1) gemm_gu_f16(void)
{
    const int e = blockIdx.z;
    const int n_e = (e < NEXP) ? g_count[e] : T_TOK;
    const int m0 = blockIdx.y * 128;
    if (m0 >= n_e) return;
    const int base = g_rowbase[e];
    const __half* __restrict__ Bg = (e < NEXP) ? (g_gWt + (size_t)e * IDIM * HDIM) : g_sgWt;
    const __half* __restrict__ Bu = (e < NEXP) ? (g_uWt + (size_t)e * IDIM * HDIM) : g_suWt;
    const int n0 = blockIdx.x * 128;

    const int tid  = threadIdx.x;
    const int warp = tid >> 5, lane = tid & 31;
    const int gi = lane >> 2, tig = lane & 3;
    const int wm = (warp & 3) * 32, wn = (warp >> 2) * 32;

    extern __shared__ __half sh[];
    __half* As  = sh;
    __half* Bgs = sh + NSTG * TILE_H;
    __half* Bus = sh + 2 * NSTG * TILE_H;
    const uint32_t uA = (uint32_t)__cvta_generic_to_shared(As);
    const uint32_t uG = (uint32_t)__cvta_generic_to_shared(Bgs);
    const uint32_t uU = (uint32_t)__cvta_generic_to_shared(Bus);

    const int pr0 = tid >> 3, pch = tid & 7;
    const __half* arow0;
    const __half* arow1;
    {
        int t0 = (m0 + pr0 < n_e)      ? g_ctok[base + m0 + pr0]      : g_ctok[base];
        int t1 = (m0 + pr0 + 64 < n_e) ? g_ctok[base + m0 + pr0 + 64] : g_ctok[base];
        arow0 = g_Xh + (size_t)t0 * HDIM + pch * 8;
        arow1 = g_Xh + (size_t)t1 * HDIM + pch * 8;
    }
    const __half* bgrow = Bg + (size_t)(n0 + pr0) * HDIM + pch * 8;
    const __half* burow = Bu + (size_t)(n0 + pr0) * HDIM + pch * 8;
    const size_t BROW64 = (size_t)64 * HDIM;
    const uint32_t d0 = (uint32_t)(pr0 * PADH + pch * 8) * 2;
    const uint32_t d1 = d0 + (uint32_t)(64 * PADH) * 2;

    float dg[2][4][4], du[2][4][4];
#pragma unroll
    for (int i = 0; i < 2; i++)
#pragma unroll
        for (int j = 0; j < 4; j++)
#pragma unroll
            for (int c = 0; c < 4; c++) { dg[i][j][c] = 0.f; du[i][j][c] = 0.f; }

    auto issue = [&](int kt, int s) {
        const int ko = kt * 64;
        const uint32_t bo = (uint32_t)(s * TILE_H * 2);
        cp_async16(uA + bo + d0, arow0 + ko);
        cp_async16(uA + bo + d1, arow1 + ko);
        cp_async16(uG + bo + d0, bgrow + ko);
        cp_async16(uG + bo + d1, bgrow + BROW64 + ko);
        cp_async16(uU + bo + d0, burow + ko);
        cp_async16(uU + bo + d1, burow + BROW64 + ko);
        cp_commit();
    };

    const int NK = HDIM / 64;   // 16
    issue(0, 0);
    issue(1, 1);
    int sbuf = 0;
    for (int kt = 0; kt < NK; kt++) {
        if (kt + 1 < NK) cp_wait<1>(); else cp_wait<0>();
        __syncthreads();
        if (kt + 2 < NK) {
            int s2 = sbuf + 2; if (s2 >= NSTG) s2 -= NSTG;
            issue(kt + 2, s2);
        }
        const __half* Ab = As  + sbuf * TILE_H;
        const __half* Gb = Bgs + sbuf * TILE_H;
        const __half* Ub = Bus + sbuf * TILE_H;
#pragma unroll
        for (int ks = 0; ks < 4; ks++) {
            const int kc = ks * 16 + 2 * tig;
            uint32_t af[2][4];
#pragma unroll
            for (int ms = 0; ms < 2; ms++) {
                const int mB = wm + ms * 16;
                af[ms][0] = *(const uint32_t*)&Ab[(mB + gi)     * PADH + kc];
                af[ms][1] = *(const uint32_t*)&Ab[(mB + 8 + gi) * PADH + kc];
                af[ms][2] = *(const uint32_t*)&Ab[(mB + gi)     * PADH + kc + 8];
                af[ms][3] = *(const uint32_t*)&Ab[(mB + 8 + gi) * PADH + kc + 8];
            }
            uint32_t bf[4][2];
#pragma unroll
            for (int ns = 0; ns < 4; ns++) {
                const int nB = wn + ns * 8 + gi;
                bf[ns][0] = *(const uint32_t*)&Gb[nB * PADH + kc];
                bf[ns][1] = *(const uint32_t*)&Gb[nB * PADH + kc + 8];
            }
#pragma unroll
            for (int ms = 0; ms < 2; ms++)
#pragma unroll
                for (int ns = 0; ns < 4; ns++)
                    mma_f16(dg[ms][ns], af[ms], bf[ns]);
#pragma unroll
            for (int ns = 0; ns < 4; ns++) {
                const int nB = wn + ns * 8 + gi;
                bf[ns][0] = *(const uint32_t*)&Ub[nB * PADH + kc];
                bf[ns][1] = *(const uint32_t*)&Ub[nB * PADH + kc + 8];
            }
#pragma unroll
            for (int ms = 0; ms < 2; ms++)
#pragma unroll
                for (int ns = 0; ns < 4; ns++)
                    mma_f16(du[ms][ns], af[ms], bf[ns]);
        }
        if (++sbuf == NSTG) sbuf = 0;
    }

#pragma unroll
    for (int ms = 0; ms < 2; ms++) {
#pragma unroll
        for (int hh = 0; hh < 2; hh++) {
            const int r = m0 + wm + ms * 16 + hh * 8 + gi;
            if (r < n_e) {
                const int row = base + r;
                const float w = g_cwgt[row];
                __half* C = g_Gh + (size_t)row * IDIM + n0 + wn;
#pragma unroll
                for (int ns = 0; ns < 4; ns++) {
                    float g0 = dg[ms][ns][2 * hh],     g1 = dg[ms][ns][2 * hh + 1];
                    float u0 = du[ms][ns][2 * hh],     u1 = du[ms][ns][2 * hh + 1];
                    float h0 = w * u0 * g0 / (1.f + __expf(-g0));
                    float h1 = w * u1 * g1 / (1.f + __expf(-g1));
                    *(__half2*)(C + ns * 8 + 2 * tig) = __floats2half2_rn(h0, h1);
                }
            }
        }
    }
}

// ============================================================================
// fp16 down GEMM + scatter. 256 thr (8 warps, 4m x 2n), warp 32x64,
// 2 CTAs/SM. K-tile 64, 3-stage pipeline. Epilogue: vectorized red.v2.f32.
// ============================================================================
__global__ void __launch_bounds__(256, 2) gemm_down_f16(float* __restrict__ out)
{
    const int e = blockIdx.z;
    const int n_e = (e < NEXP) ? g_count[e] : T_TOK;
    const int m0 = blockIdx.y * 128;
    if (m0 >= n_e) return;
    const int base = g_rowbase[e];
    const __half* __restrict__ B = (e < NEXP) ? (g_dWt + (size_t)e * HDIM * IDIM) : g_sdWt;
    const int n0 = blockIdx.x * 128;

    const int tid  = threadIdx.x;
    const int warp = tid >> 5, lane = tid & 31;
    const int gi = lane >> 2, tig = lane & 3;
    const int wm = (warp & 3) * 32, wn = (warp >> 2) * 64;

    extern __shared__ __half sh[];
    __half* As = sh;
    __half* Bs = sh + NSTG * TILE_H;
    const uint32_t uA = (uint32_t)__cvta_generic_to_shared(As);
    const uint32_t uB = (uint32_t)__cvta_generic_to_shared(Bs);

    const int pr0 = tid >> 3, pch = tid & 7;
    const __half* arow = g_Gh + (size_t)(base + m0 + pr0) * IDIM + pch * 8;
    const __half* brow = B + (size_t)(n0 + pr0) * IDIM + pch * 8;
    const size_t ROW32 = (size_t)32 * IDIM;
    const uint32_t ds0 = (uint32_t)(pr0 * PADH + pch * 8) * 2;
    const uint32_t SROW32 = (uint32_t)(32 * PADH) * 2;

    float d[2][8][4];
#pragma unroll
    for (int i = 0; i < 2; i++)
#pragma unroll
        for (int j = 0; j < 8; j++)
#pragma unroll
            for (int c = 0; c < 4; c++) d[i][j][c] = 0.f;

    auto issue = [&](int kt, int s) {
        const int ko = kt * 64;
        const uint32_t bo = (uint32_t)(s * TILE_H * 2);
#pragma unroll
        for (int c = 0; c < 4; c++) {
            cp_async16(uA + bo + ds0 + c * SROW32, arow + c * ROW32 + ko);
            cp_async16(uB + bo + ds0 + c * SROW32, brow + c * ROW32 + ko);
        }
        cp_commit();
    };

    const int NK = IDIM / 64;   // 32
    issue(0, 0);
    issue(1, 1);
    int sbuf = 0;
    for (int kt = 0; kt < NK; kt++) {
        if (kt + 1 < NK) cp_wait<1>(); else cp_wait<0>();
        __syncthreads();
        if (kt + 2 < NK) {
            int s2 = sbuf + 2; if (s2 >= NSTG) s2 -= NSTG;
            issue(kt + 2, s2);
        }
        const __half* Ab = As + sbuf * TILE_H;
        const __half* Bb = Bs + sbuf * TILE_H;
#pragma unroll
        for (int ks = 0; ks < 4; ks++) {
            const int kc = ks * 16 + 2 * tig;
            uint32_t af[2][4];
#pragma unroll
            for (int ms = 0; ms < 2; ms++) {
                const int mB = wm + ms * 16;
                af[ms][0] = *(const uint32_t*)&Ab[(mB + gi)     * PADH + kc];
                af[ms][1] = *(const uint32_t*)&Ab[(mB + 8 + gi) * PADH + kc];
                af[ms][2] = *(const uint32_t*)&Ab[(mB + gi)     * PADH + kc + 8];
                af[ms][3] = *(const uint32_t*)&Ab[(mB + 8 + gi) * PADH + kc + 8];
            }
            uint32_t bf[8][2];
#pragma unroll
            for (int ns = 0; ns < 8; ns++) {
                const int nB = wn + ns * 8 + gi;
                bf[ns][0] = *(const uint32_t*)&Bb[nB * PADH + kc];
                bf[ns][1] = *(const uint32_t*)&Bb[nB * PADH + kc + 8];
            }
#pragma unroll
            for (int ms = 0; ms < 2; ms++)
#pragma unroll
                for (int ns = 0; ns < 8; ns++)
                    mma_f16(d[ms][ns], af[ms], bf[ns]);
        }
        if (++sbuf == NSTG) sbuf = 0;
    }

    // epilogue: vectorized scatter-accumulate (red.v2.f32; 8B-aligned pairs)
#pragma unroll
    for (int ms = 0; ms < 2; ms++) {
        const int r0 = m0 + wm + ms * 16 + gi;
        const int r1 = r0 + 8;
        if (r0 < n_e) {
            const int tok = g_ctok[base + r0];
            float* o = out + (size_t)tok * HDIM + n0 + wn;
#pragma unroll
            for (int ns = 0; ns < 8; ns++)
                red_add_f32x2(o + ns * 8 + 2 * tig, d[ms][ns][0], d[ms][ns][1]);
        }
        if (r1 < n_e) {
            const int tok = g_ctok[base + r1];
            float* o = out + (size_t)tok * HDIM + n0 + wn;
#pragma unroll
            for (int ns = 0; ns < 8; ns++)
                red_add_f32x2(o + ns * 8 + 2 * tig, d[ms][ns][2], d[ms][ns][3]);
        }
    }
}

// ---------------- host launcher ----------------------------------------------
extern "C" void kernel_launch(void* const* d_in, const int* in_sizes, int n_in,
                              void* d_out, int out_size)
{
    const float* x       = (const float*)d_in[0];
    const float* rw      = (const float*)d_in[1];
    const float* gate_w  = (const float*)d_in[2];
    const float* up_w    = (const float*)d_in[3];
    const float* down_w  = (const float*)d_in[4];
    const float* sgate_w = (const float*)d_in[5];
    const float* sup_w   = (const float*)d_in[6];
    const float* sdown_w = (const float*)d_in[7];
    float* out = (float*)d_out;

    void* cnt_addr = nullptr;
    cudaGetSymbolAddress(&cnt_addr, g_count);

    cudaFuncSetAttribute(gemm_gu_f16,
                         cudaFuncAttributeMaxDynamicSharedMemorySize, GU_SMEMB);
    cudaFuncSetAttribute(gemm_down_f16,
                         cudaFuncAttributeMaxDynamicSharedMemorySize, DN_SMEMB);

    dim3 tb(32, 8);
    dim3 grid_gu(IDIM / 128, T_TOK / 128, NEXP + 1);
    dim3 grid_dn(HDIM / 128, T_TOK / 128, NEXP + 1);

    // single-stream schedule (R10 optimum): nothing overlaps the GEMMs
    cudaMemsetAsync(out, 0, (size_t)T_TOK * HDIM * sizeof(float));
    cudaMemsetAsync(cnt_addr, 0, NEXP * sizeof(int));
    router_kernel<<<ROUTER_BLOCKS, 256>>>(x, rw, out);
    finalize_kernel<<<1, 288>>>(out);
    compact_kernel<<<((NEXP + 1) * T_TOK) / 256, 256>>>();
    cvt_gu_w_kernel<<<dim3(IDIM / 32, HDIM / 64, 18), tb>>>(gate_w, up_w, sgate_w, sup_w);
    cvt_dn_w_kernel<<<dim3(HDIM / 32, IDIM / 64, 9),  tb>>>(down_w, sdown_w);
    gemm_gu_f16<<<grid_gu, 512, GU_SMEMB>>>();
    gemm_down_f16<<<grid_dn, 256, DN_SMEMB>>>(out);
}

// round 15
// speedup vs baseline: 1.0530x; 1.0065x over previous
#include <cuda_runtime.h>
#include <cuda_fp16.h>
#include <cstdint>
#include <cstddef>

// Problem constants
#define T_TOK   4096
#define HDIM    1024
#define IDIM    2048
#define NEXP    8
#define TOPK    2
#define NROWS_ROUTED (T_TOK * TOPK)         // 8192
#define NROWS_TOTAL  (NROWS_ROUTED + T_TOK) // 12288
#define ROUTER_BLOCKS (T_TOK / 8)           // 512

#define OUT_AUX    (T_TOK * HDIM)
#define OUT_Z      (OUT_AUX + 1)
#define OUT_LOGITS (OUT_AUX + 2)

// ---------------- scratch ----------------------------------------------------
__device__ int   g_count[NEXP];
__device__ int   g_list[NEXP * T_TOK];
__device__ float g_wgt [NEXP * T_TOK];
__device__ int   g_rowbase[NEXP + 1];
__device__ int   g_ctok[NROWS_TOTAL];
__device__ float g_cwgt[NROWS_TOTAL];
__device__ float g_pp[ROUTER_BLOCKS * NEXP];
__device__ float g_pl[ROUTER_BLOCKS];

// fp16 operands (16B-aligned for cp.async)
__device__ __align__(16) __half g_Xh [(size_t)T_TOK * HDIM];
__device__ __align__(16) __half g_Gh [(size_t)NROWS_TOTAL * IDIM];
__device__ __align__(16) __half g_gWt[(size_t)NEXP * IDIM * HDIM];  // [e][N][K]
__device__ __align__(16) __half g_uWt[(size_t)NEXP * IDIM * HDIM];
__device__ __align__(16) __half g_dWt[(size_t)NEXP * HDIM * IDIM];
__device__ __align__(16) __half g_sgWt[(size_t)IDIM * HDIM];
__device__ __align__(16) __half g_suWt[(size_t)IDIM * HDIM];
__device__ __align__(16) __half g_sdWt[(size_t)HDIM * IDIM];

// ---------------- helpers -----------------------------------------------------
__device__ __forceinline__ void cp_async16(uint32_t s, const void* g) {
    asm volatile("cp.async.cg.shared.global [%0], [%1], 16;\n" :: "r"(s), "l"(g));
}
__device__ __forceinline__ void cp_commit() {
    asm volatile("cp.async.commit_group;\n");
}
template <int N>
__device__ __forceinline__ void cp_wait() {
    asm volatile("cp.async.wait_group %0;\n" :: "n"(N));
}
__device__ __forceinline__ void mma_f16(float* d, const uint32_t* a, const uint32_t* b) {
    asm volatile(
        "mma.sync.aligned.m16n8k16.row.col.f32.f16.f16.f32 "
        "{%0,%1,%2,%3},{%4,%5,%6,%7},{%8,%9},{%0,%1,%2,%3};"
        : "+f"(d[0]), "+f"(d[1]), "+f"(d[2]), "+f"(d[3])
        : "r"(a[0]), "r"(a[1]), "r"(a[2]), "r"(a[3]), "r"(b[0]), "r"(b[1]));
}
// vectorized fp32 reduction (sm_90+): one RED op per value pair
__device__ __forceinline__ void red_add_f32x2(float* addr, float a, float b) {
    asm volatile("red.global.add.v2.f32 [%0], {%1, %2};"
                 :: "l"(addr), "f"(a), "f"(b) : "memory");
}

// ---------------- router (+ fused X->fp16 conversion) -------------------------
__global__ void __launch_bounds__(256) router_kernel(
    const float* __restrict__ x, const float* __restrict__ rw,
    float* __restrict__ out)
{
    const int warp = threadIdx.x >> 5, lane = threadIdx.x & 31;
    const int t = blockIdx.x * 8 + warp;

    float acc[NEXP];
#pragma unroll
    for (int e = 0; e < NEXP; e++) acc[e] = 0.f;

    const float* xr = x + (size_t)t * HDIM;
    for (int h = lane; h < HDIM; h += 32) {
        float xv = xr[h];
        const float* r = rw + (size_t)h * NEXP;
#pragma unroll
        for (int e = 0; e < NEXP; e++) acc[e] += xv * r[e];
    }
    // fused fp16 conversion of this token's row (L2-hot)
    {
        __half2* dst = (__half2*)(g_Xh + (size_t)t * HDIM);
        for (int h = lane; h < HDIM / 2; h += 32) {
            float2 v = *(const float2*)(xr + 2 * h);
            dst[h] = __floats2half2_rn(v.x, v.y);
        }
    }
#pragma unroll
    for (int off = 16; off > 0; off >>= 1)
#pragma unroll
        for (int e = 0; e < NEXP; e++)
            acc[e] += __shfl_xor_sync(0xFFFFFFFFu, acc[e], off);

    __shared__ float s_prob[8][NEXP];
    __shared__ float s_lse2[8];

    if (lane == 0) {
        float mx = acc[0];
#pragma unroll
        for (int e = 1; e < NEXP; e++) mx = fmaxf(mx, acc[e]);
        float p[NEXP], sum = 0.f;
#pragma unroll
        for (int e = 0; e < NEXP; e++) { p[e] = expf(acc[e] - mx); sum += p[e]; }
        float lse = logf(sum) + mx;
        s_lse2[warp] = lse * lse;
        float inv = 1.f / sum;
#pragma unroll
        for (int e = 0; e < NEXP; e++) {
            p[e] *= inv;
            s_prob[warp][e] = p[e];
            out[OUT_LOGITS + (size_t)t * NEXP + e] = acc[e];
        }
        int i1 = 0;
#pragma unroll
        for (int e = 1; e < NEXP; e++) if (p[e] > p[i1]) i1 = e;
        int i2 = (i1 == 0) ? 1 : 0;
#pragma unroll
        for (int e = 0; e < NEXP; e++) if (e != i2 && e != i1 && p[e] > p[i2]) i2 = e;
        float s2 = p[i1] + p[i2];
        float w1 = p[i1] / s2, w2 = p[i2] / s2;
        int pos1 = atomicAdd(&g_count[i1], 1);
        g_list[i1 * T_TOK + pos1] = t; g_wgt[i1 * T_TOK + pos1] = w1;
        int pos2 = atomicAdd(&g_count[i2], 1);
        g_list[i2 * T_TOK + pos2] = t; g_wgt[i2 * T_TOK + pos2] = w2;
    }
    __syncthreads();
    if (threadIdx.x == 0) {
        float ps[NEXP]; float l2 = 0.f;
#pragma unroll
        for (int e = 0; e < NEXP; e++) ps[e] = 0.f;
        for (int w = 0; w < 8; w++) {
            l2 += s_lse2[w];
#pragma unroll
            for (int e = 0; e < NEXP; e++) ps[e] += s_prob[w][e];
        }
#pragma unroll
        for (int e = 0; e < NEXP; e++) g_pp[blockIdx.x * NEXP + e] = ps[e];
        g_pl[blockIdx.x] = l2;
    }
}

// ---------------- finalize ----------------------------------------------------
__global__ void finalize_kernel(float* __restrict__ out) {
    const int warp = threadIdx.x >> 5, lane = threadIdx.x & 31;
    __shared__ float red[NEXP + 1];
    if (warp < NEXP) {
        float s = 0.f;
        for (int j = 0; j < ROUTER_BLOCKS / 32; j++)
            s += g_pp[(size_t)(lane + 32 * j) * NEXP + warp];
#pragma unroll
        for (int off = 16; off > 0; off >>= 1) s += __shfl_xor_sync(0xFFFFFFFFu, s, off);
        if (lane == 0) red[warp] = s;
    } else if (warp == NEXP) {
        float s = 0.f;
        for (int j = 0; j < ROUTER_BLOCKS / 32; j++)
            s += g_pl[lane + 32 * j];
#pragma unroll
        for (int off = 16; off > 0; off >>= 1) s += __shfl_xor_sync(0xFFFFFFFFu, s, off);
        if (lane == 0) red[NEXP] = s;
    }
    __syncthreads();
    if (threadIdx.x == 0) {
        float aux = 0.f;
        int rb = 0;
        for (int e = 0; e < NEXP; e++) {
            aux += ((float)g_count[e] / (float)(T_TOK * TOPK)) * (red[e] / (float)T_TOK);
            g_rowbase[e] = rb;
            rb += g_count[e];
        }
        g_rowbase[NEXP] = NROWS_ROUTED;
        out[OUT_AUX] = (float)NEXP * aux;
        out[OUT_Z]   = red[NEXP] / (float)T_TOK;
    }
}

// ---------------- compact -----------------------------------------------------
__global__ void compact_kernel() {
    int idx = blockIdx.x * blockDim.x + threadIdx.x;
    int e = idx / T_TOK, pos = idx % T_TOK;
    if (e < NEXP) {
        if (pos < g_count[e]) {
            int cr = g_rowbase[e] + pos;
            g_ctok[cr] = g_list[e * T_TOK + pos];
            g_cwgt[cr] = g_wgt[e * T_TOK + pos];
        }
    } else {
        g_ctok[NROWS_ROUTED + pos] = pos;
        g_cwgt[NROWS_ROUTED + pos] = 1.f;
    }
}

// ---------------- unified transpose+cvt: [K][N] f32 -> [N][K] fp16 ------------
// 64-K x 32-N tile. Global reads LDG.128 (2 float4/thread), scalar STS into
// stride-33 SMEM, fp16 writes are 128B rows (half2/thread).
// z: 0..7 gate, 8..15 up, 16 sgate, 17 sup (K=HDIM,N=IDIM; 1024 blocks/slice)
//    18..25 down, 26 sdown              (K=IDIM,N=HDIM; 1024 blocks/slice)
__global__ void __launch_bounds__(256) cvt_w_kernel(
    const float* __restrict__ gate_w, const float* __restrict__ up_w,
    const float* __restrict__ sg_w,   const float* __restrict__ su_w,
    const float* __restrict__ down_w, const float* __restrict__ sd_w)
{
    const int z = blockIdx.y;
    const int b = blockIdx.x;           // 0..1023
    const float* src; __half* dst; int K, N, n0, k0;
    if (z < 18) {
        K = HDIM; N = IDIM;
        n0 = (b & 63) * 32; k0 = (b >> 6) * 64;
        if (z < 8)        { src = gate_w + (size_t)z * HDIM * IDIM;       dst = g_gWt + (size_t)z * IDIM * HDIM; }
        else if (z < 16)  { src = up_w + (size_t)(z - 8) * HDIM * IDIM;   dst = g_uWt + (size_t)(z - 8) * IDIM * HDIM; }
        else if (z == 16) { src = sg_w; dst = g_sgWt; }
        else              { src = su_w; dst = g_suWt; }
    } else {
        K = IDIM; N = HDIM;
        n0 = (b & 31) * 32; k0 = (b >> 5) * 64;
        const int zz = z - 18;
        if (zz < 8) { src = down_w + (size_t)zz * IDIM * HDIM; dst = g_dWt + (size_t)zz * HDIM * IDIM; }
        else        { src = sd_w;  dst = g_sdWt; }
    }

    __shared__ float t[64][33];
    const int tid = threadIdx.x;
    // read phase: 512 float4 per tile, 2 per thread
#pragma unroll
    for (int c = 0; c < 2; c++) {
        int idx = c * 256 + tid;
        int r = idx >> 3, q = idx & 7;
        float4 v = *(const float4*)(src + (size_t)(k0 + r) * N + n0 + q * 4);
        t[r][q * 4 + 0] = v.x;
        t[r][q * 4 + 1] = v.y;
        t[r][q * 4 + 2] = v.z;
        t[r][q * 4 + 3] = v.w;
    }
    __syncthreads();
    // write phase: 128B fp16 rows
    const int tx = tid & 31, ty = tid >> 5;
#pragma unroll
    for (int i = 0; i < 32; i += 8) {
        float a = t[2 * tx][ty + i];
        float c = t[2 * tx + 1][ty + i];
        *(__half2*)&dst[(size_t)(n0 + ty + i) * K + k0 + 2 * tx] =
            __floats2half2_rn(a, c);
    }
}

// ============================================================================
// fp16 fused gate+up+act GEMM. 512 thr (16 warps, 4m x 4n), block 128x128,
// warp 32x32 each. K-tile 64, 3-stage cp.async pipeline, one barrier per kt.
// ============================================================================
#define PADH 72
#define TILE_H (128 * PADH)
#define NSTG 3
#define GU_SMEMB (NSTG * 3 * TILE_H * 2)   // 165888 B
#define DN_SMEMB (NSTG * 2 * TILE_H * 2)   // 110592 B

__global__ void __launch_bounds__(512, 1) gemm_gu_f16(void)
{
    const int e = blockIdx.z;
    const int n_e = (e < NEXP) ? g_count[e] : T_TOK;
    const int m0 = blockIdx.y * 128;
    if (m0 >= n_e) return;
    const int base = g_rowbase[e];
    const __half* __restrict__ Bg = (e < NEXP) ? (g_gWt + (size_t)e * IDIM * HDIM) : g_sgWt;
    const __half* __restrict__ Bu = (e < NEXP) ? (g_uWt + (size_t)e * IDIM * HDIM) : g_suWt;
    const int n0 = blockIdx.x * 128;

    const int tid  = threadIdx.x;
    const int warp = tid >> 5, lane = tid & 31;
    const int gi = lane >> 2, tig = lane & 3;
    const int wm = (warp & 3) * 32, wn = (warp >> 2) * 32;

    extern __shared__ __half sh[];
    __half* As  = sh;
    __half* Bgs = sh + NSTG * TILE_H;
    __half* Bus = sh + 2 * NSTG * TILE_H;
    const uint32_t uA = (uint32_t)__cvta_generic_to_shared(As);
    const uint32_t uG = (uint32_t)__cvta_generic_to_shared(Bgs);
    const uint32_t uU = (uint32_t)__cvta_generic_to_shared(Bus);

    const int pr0 = tid >> 3, pch = tid & 7;
    const __half* arow0;
    const __half* arow1;
    {
        int t0 = (m0 + pr0 < n_e)      ? g_ctok[base + m0 + pr0]      : g_ctok[base];
        int t1 = (m0 + pr0 + 64 < n_e) ? g_ctok[base + m0 + pr0 + 64] : g_ctok[base];
        arow0 = g_Xh + (size_t)t0 * HDIM + pch * 8;
        arow1 = g_Xh + (size_t)t1 * HDIM + pch * 8;
    }
    const __half* bgrow = Bg + (size_t)(n0 + pr0) * HDIM + pch * 8;
    const __half* burow = Bu + (size_t)(n0 + pr0) * HDIM + pch * 8;
    const size_t BROW64 = (size_t)64 * HDIM;
    const uint32_t d0 = (uint32_t)(pr0 * PADH + pch * 8) * 2;
    const uint32_t d1 = d0 + (uint32_t)(64 * PADH) * 2;

    float dg[2][4][4], du[2][4][4];
#pragma unroll
    for (int i = 0; i < 2; i++)
#pragma unroll
        for (int j = 0; j < 4; j++)
#pragma unroll
            for (int c = 0; c < 4; c++) { dg[i][j][c] = 0.f; du[i][j][c] = 0.f; }

    auto issue = [&](int kt, int s) {
        const int ko = kt * 64;
        const uint32_t bo = (uint32_t)(s * TILE_H * 2);
        cp_async16(uA + bo + d0, arow0 + ko);
        cp_async16(uA + bo + d1, arow1 + ko);
        cp_async16(uG + bo + d0, bgrow + ko);
        cp_async16(uG + bo + d1, bgrow + BROW64 + ko);
        cp_async16(uU + bo + d0, burow + ko);
        cp_async16(uU + bo + d1, burow + BROW64 + ko);
        cp_commit();
    };

    const int NK = HDIM / 64;   // 16
    issue(0, 0);
    issue(1, 1);
    int sbuf = 0;
    for (int kt = 0; kt < NK; kt++) {
        if (kt + 1 < NK) cp_wait<1>(); else cp_wait<0>();
        __syncthreads();
        if (kt + 2 < NK) {
            int s2 = sbuf + 2; if (s2 >= NSTG) s2 -= NSTG;
            issue(kt + 2, s2);
        }
        const __half* Ab = As  + sbuf * TILE_H;
        const __half* Gb = Bgs + sbuf * TILE_H;
        const __half* Ub = Bus + sbuf * TILE_H;
#pragma unroll
        for (int ks = 0; ks < 4; ks++) {
            const int kc = ks * 16 + 2 * tig;
            uint32_t af[2][4];
#pragma unroll
            for (int ms = 0; ms < 2; ms++) {
                const int mB = wm + ms * 16;
                af[ms][0] = *(const uint32_t*)&Ab[(mB + gi)     * PADH + kc];
                af[ms][1] = *(const uint32_t*)&Ab[(mB + 8 + gi) * PADH + kc];
                af[ms][2] = *(const uint32_t*)&Ab[(mB + gi)     * PADH + kc + 8];
                af[ms][3] = *(const uint32_t*)&Ab[(mB + 8 + gi) * PADH + kc + 8];
            }
            uint32_t bf[4][2];
#pragma unroll
            for (int ns = 0; ns < 4; ns++) {
                const int nB = wn + ns * 8 + gi;
                bf[ns][0] = *(const uint32_t*)&Gb[nB * PADH + kc];
                bf[ns][1] = *(const uint32_t*)&Gb[nB * PADH + kc + 8];
            }
#pragma unroll
            for (int ms = 0; ms < 2; ms++)
#pragma unroll
                for (int ns = 0; ns < 4; ns++)
                    mma_f16(dg[ms][ns], af[ms], bf[ns]);
#pragma unroll
            for (int ns = 0; ns < 4; ns++) {
                const int nB = wn + ns * 8 + gi;
                bf[ns][0] = *(const uint32_t*)&Ub[nB * PADH + kc];
                bf[ns][1] = *(const uint32_t*)&Ub[nB * PADH + kc + 8];
            }
#pragma unroll
            for (int ms = 0; ms < 2; ms++)
#pragma unroll
                for (int ns = 0; ns < 4; ns++)
                    mma_f16(du[ms][ns], af[ms], bf[ns]);
        }
        if (++sbuf == NSTG) sbuf = 0;
    }

#pragma unroll
    for (int ms = 0; ms < 2; ms++) {
#pragma unroll
        for (int hh = 0; hh < 2; hh++) {
            const int r = m0 + wm + ms * 16 + hh * 8 + gi;
            if (r < n_e) {
                const int row = base + r;
                const float w = g_cwgt[row];
                __half* C = g_Gh + (size_t)row * IDIM + n0 + wn;
#pragma unroll
                for (int ns = 0; ns < 4; ns++) {
                    float g0 = dg[ms][ns][2 * hh],     g1 = dg[ms][ns][2 * hh + 1];
                    float u0 = du[ms][ns][2 * hh],     u1 = du[ms][ns][2 * hh + 1];
                    float h0 = w * u0 * g0 / (1.f + __expf(-g0));
                    float h1 = w * u1 * g1 / (1.f + __expf(-g1));
                    *(__half2*)(C + ns * 8 + 2 * tig) = __floats2half2_rn(h0, h1);
                }
            }
        }
    }
}

// ============================================================================
// fp16 down GEMM + scatter. 256 thr (8 warps, 4m x 2n), warp 32x64,
// 2 CTAs/SM. K-tile 64, 3-stage pipeline. Epilogue: vectorized red.v2.f32.
// ============================================================================
__global__ void __launch_bounds__(256, 2) gemm_down_f16(float* __restrict__ out)
{
    const int e = blockIdx.z;
    const int n_e = (e < NEXP) ? g_count[e] : T_TOK;
    const int m0 = blockIdx.y * 128;
    if (m0 >= n_e) return;
    const int base = g_rowbase[e];
    const __half* __restrict__ B = (e < NEXP) ? (g_dWt + (size_t)e * HDIM * IDIM) : g_sdWt;
    const int n0 = blockIdx.x * 128;

    const int tid  = threadIdx.x;
    const int warp = tid >> 5, lane = tid & 31;
    const int gi = lane >> 2, tig = lane & 3;
    const int wm = (warp & 3) * 32, wn = (warp >> 2) * 64;

    extern __shared__ __half sh[];
    __half* As = sh;
    __half* Bs = sh + NSTG * TILE_H;
    const uint32_t uA = (uint32_t)__cvta_generic_to_shared(As);
    const uint32_t uB = (uint32_t)__cvta_generic_to_shared(Bs);

    const int pr0 = tid >> 3, pch = tid & 7;
    const __half* arow = g_Gh + (size_t)(base + m0 + pr0) * IDIM + pch * 8;
    const __half* brow = B + (size_t)(n0 + pr0) * IDIM + pch * 8;
    const size_t ROW32 = (size_t)32 * IDIM;
    const uint32_t ds0 = (uint32_t)(pr0 * PADH + pch * 8) * 2;
    const uint32_t SROW32 = (uint32_t)(32 * PADH) * 2;

    float d[2][8][4];
#pragma unroll
    for (int i = 0; i < 2; i++)
#pragma unroll
        for (int j = 0; j < 8; j++)
#pragma unroll
            for (int c = 0; c < 4; c++) d[i][j][c] = 0.f;

    auto issue = [&](int kt, int s) {
        const int ko = kt * 64;
        const uint32_t bo = (uint32_t)(s * TILE_H * 2);
#pragma unroll
        for (int c = 0; c < 4; c++) {
            cp_async16(uA + bo + ds0 + c * SROW32, arow + c * ROW32 + ko);
            cp_async16(uB + bo + ds0 + c * SROW32, brow + c * ROW32 + ko);
        }
        cp_commit();
    };

    const int NK = IDIM / 64;   // 32
    issue(0, 0);
    issue(1, 1);
    int sbuf = 0;
    for (int kt = 0; kt < NK; kt++) {
        if (kt + 1 < NK) cp_wait<1>(); else cp_wait<0>();
        __syncthreads();
        if (kt + 2 < NK) {
            int s2 = sbuf + 2; if (s2 >= NSTG) s2 -= NSTG;
            issue(kt + 2, s2);
        }
        const __half* Ab = As + sbuf * TILE_H;
        const __half* Bb = Bs + sbuf * TILE_H;
#pragma unroll
        for (int ks = 0; ks < 4; ks++) {
            const int kc = ks * 16 + 2 * tig;
            uint32_t af[2][4];
#pragma unroll
            for (int ms = 0; ms < 2; ms++) {
                const int mB = wm + ms * 16;
                af[ms][0] = *(const uint32_t*)&Ab[(mB + gi)     * PADH + kc];
                af[ms][1] = *(const uint32_t*)&Ab[(mB + 8 + gi) * PADH + kc];
                af[ms][2] = *(const uint32_t*)&Ab[(mB + gi)     * PADH + kc + 8];
                af[ms][3] = *(const uint32_t*)&Ab[(mB + 8 + gi) * PADH + kc + 8];
            }
            uint32_t bf[8][2];
#pragma unroll
            for (int ns = 0; ns < 8; ns++) {
                const int nB = wn + ns * 8 + gi;
                bf[ns][0] = *(const uint32_t*)&Bb[nB * PADH + kc];
                bf[ns][1] = *(const uint32_t*)&Bb[nB * PADH + kc + 8];
            }
#pragma unroll
            for (int ms = 0; ms < 2; ms++)
#pragma unroll
                for (int ns = 0; ns < 8; ns++)
                    mma_f16(d[ms][ns], af[ms], bf[ns]);
        }
        if (++sbuf == NSTG) sbuf = 0;
    }

    // epilogue: vectorized scatter-accumulate (red.v2.f32; 8B-aligned pairs)
#pragma unroll
    for (int ms = 0; ms < 2; ms++) {
        const int r0 = m0 + wm + ms * 16 + gi;
        const int r1 = r0 + 8;
        if (r0 < n_e) {
            const int tok = g_ctok[base + r0];
            float* o = out + (size_t)tok * HDIM + n0 + wn;
#pragma unroll
            for (int ns = 0; ns < 8; ns++)
                red_add_f32x2(o + ns * 8 + 2 * tig, d[ms][ns][0], d[ms][ns][1]);
        }
        if (r1 < n_e) {
            const int tok = g_ctok[base + r1];
            float* o = out + (size_t)tok * HDIM + n0 + wn;
#pragma unroll
            for (int ns = 0; ns < 8; ns++)
                red_add_f32x2(o + ns * 8 + 2 * tig, d[ms][ns][2], d[ms][ns][3]);
        }
    }
}

// ---------------- host launcher ----------------------------------------------
extern "C" void kernel_launch(void* const* d_in, const int* in_sizes, int n_in,
                              void* d_out, int out_size)
{
    const float* x       = (const float*)d_in[0];
    const float* rw      = (const float*)d_in[1];
    const float* gate_w  = (const float*)d_in[2];
    const float* up_w    = (const float*)d_in[3];
    const float* down_w  = (const float*)d_in[4];
    const float* sgate_w = (const float*)d_in[5];
    const float* sup_w   = (const float*)d_in[6];
    const float* sdown_w = (const float*)d_in[7];
    float* out = (float*)d_out;

    void* cnt_addr = nullptr;
    cudaGetSymbolAddress(&cnt_addr, g_count);

    cudaFuncSetAttribute(gemm_gu_f16,
                         cudaFuncAttributeMaxDynamicSharedMemorySize, GU_SMEMB);
    cudaFuncSetAttribute(gemm_down_f16,
                         cudaFuncAttributeMaxDynamicSharedMemorySize, DN_SMEMB);

    dim3 grid_gu(IDIM / 128, T_TOK / 128, NEXP + 1);
    dim3 grid_dn(HDIM / 128, T_TOK / 128, NEXP + 1);

    // single-stream schedule: nothing overlaps the GEMMs
    cudaMemsetAsync(out, 0, (size_t)T_TOK * HDIM * sizeof(float));
    cudaMemsetAsync(cnt_addr, 0, NEXP * sizeof(int));
    router_kernel<<<ROUTER_BLOCKS, 256>>>(x, rw, out);
    finalize_kernel<<<1, 288>>>(out);
    compact_kernel<<<((NEXP + 1) * T_TOK) / 256, 256>>>();
    cvt_w_kernel<<<dim3(1024, 27), 256>>>(gate_w, up_w, sgate_w, sup_w,
                                          down_w, sdown_w);
    gemm_gu_f16<<<grid_gu, 512, GU_SMEMB>>>();
    gemm_down_f16<<<grid_dn, 256, DN_SMEMB>>>(out);
}

// round 16
// speedup vs baseline: 1.0618x; 1.0083x over previous
#include <cuda_runtime.h>
#include <cuda_fp16.h>
#include <cstdint>
#include <cstddef>

// Problem constants
#define T_TOK   4096
#define HDIM    1024
#define IDIM    2048
#define NEXP    8
#define TOPK    2
#define NROWS_ROUTED (T_TOK * TOPK)         // 8192
#define NROWS_TOTAL  (NROWS_ROUTED + T_TOK) // 12288
#define ROUTER_BLOCKS (T_TOK / 8)           // 512

#define OUT_AUX    (T_TOK * HDIM)
#define OUT_Z      (OUT_AUX + 1)
#define OUT_LOGITS (OUT_AUX + 2)

// ---------------- scratch ----------------------------------------------------
__device__ int   g_count[NEXP];
__device__ int   g_list[NEXP * T_TOK];
__device__ float g_wgt [NEXP * T_TOK];
__device__ int   g_rowbase[NEXP + 1];
__device__ int   g_ctok[NROWS_TOTAL];
__device__ float g_cwgt[NROWS_TOTAL];
__device__ float g_pp[ROUTER_BLOCKS * NEXP];
__device__ float g_pl[ROUTER_BLOCKS];

// fp16 operands (16B-aligned for cp.async)
__device__ __align__(16) __half g_Xh [(size_t)T_TOK * HDIM];
__device__ __align__(16) __half g_Gh [(size_t)NROWS_TOTAL * IDIM];
__device__ __align__(16) __half g_gWt[(size_t)NEXP * IDIM * HDIM];  // [e][N][K]
__device__ __align__(16) __half g_uWt[(size_t)NEXP * IDIM * HDIM];
__device__ __align__(16) __half g_dWt[(size_t)NEXP * HDIM * IDIM];
__device__ __align__(16) __half g_sgWt[(size_t)IDIM * HDIM];
__device__ __align__(16) __half g_suWt[(size_t)IDIM * HDIM];
__device__ __align__(16) __half g_sdWt[(size_t)HDIM * IDIM];

// ---------------- helpers -----------------------------------------------------
__device__ __forceinline__ void cp_async16(uint32_t s, const void* g) {
    asm volatile("cp.async.cg.shared.global [%0], [%1], 16;\n" :: "r"(s), "l"(g));
}
__device__ __forceinline__ void cp_commit() {
    asm volatile("cp.async.commit_group;\n");
}
template <int N>
__device__ __forceinline__ void cp_wait() {
    asm volatile("cp.async.wait_group %0;\n" :: "n"(N));
}
__device__ __forceinline__ void mma_f16(float* d, const uint32_t* a, const uint32_t* b) {
    asm volatile(
        "mma.sync.aligned.m16n8k16.row.col.f32.f16.f16.f32 "
        "{%0,%1,%2,%3},{%4,%5,%6,%7},{%8,%9},{%0,%1,%2,%3};"
        : "+f"(d[0]), "+f"(d[1]), "+f"(d[2]), "+f"(d[3])
        : "r"(a[0]), "r"(a[1]), "r"(a[2]), "r"(a[3]), "r"(b[0]), "r"(b[1]));
}
// vectorized fp32 reduction (sm_90+): one RED op per value pair
__device__ __forceinline__ void red_add_f32x2(float* addr, float a, float b) {
    asm volatile("red.global.add.v2.f32 [%0], {%1, %2};"
                 :: "l"(addr), "f"(a), "f"(b) : "memory");
}

// ---------------- router (+ fused X->fp16 conversion) -------------------------
__global__ void __launch_bounds__(256) router_kernel(
    const float* __restrict__ x, const float* __restrict__ rw,
    float* __restrict__ out)
{
    const int warp = threadIdx.x >> 5, lane = threadIdx.x & 31;
    const int t = blockIdx.x * 8 + warp;

    float acc[NEXP];
#pragma unroll
    for (int e = 0; e < NEXP; e++) acc[e] = 0.f;

    const float* xr = x + (size_t)t * HDIM;
    for (int h = lane; h < HDIM; h += 32) {
        float xv = xr[h];
        const float* r = rw + (size_t)h * NEXP;
#pragma unroll
        for (int e = 0; e < NEXP; e++) acc[e] += xv * r[e];
    }
    // fused fp16 conversion of this token's row (L2-hot)
    {
        __half2* dst = (__half2*)(g_Xh + (size_t)t * HDIM);
        for (int h = lane; h < HDIM / 2; h += 32) {
            float2 v = *(const float2*)(xr + 2 * h);
            dst[h] = __floats2half2_rn(v.x, v.y);
        }
    }
#pragma unroll
    for (int off = 16; off > 0; off >>= 1)
#pragma unroll
        for (int e = 0; e < NEXP; e++)
            acc[e] += __shfl_xor_sync(0xFFFFFFFFu, acc[e], off);

    __shared__ float s_prob[8][NEXP];
    __shared__ float s_lse2[8];

    if (lane == 0) {
        float mx = acc[0];
#pragma unroll
        for (int e = 1; e < NEXP; e++) mx = fmaxf(mx, acc[e]);
        float p[NEXP], sum = 0.f;
#pragma unroll
        for (int e = 0; e < NEXP; e++) { p[e] = expf(acc[e] - mx); sum += p[e]; }
        float lse = logf(sum) + mx;
        s_lse2[warp] = lse * lse;
        float inv = 1.f / sum;
#pragma unroll
        for (int e = 0; e < NEXP; e++) {
            p[e] *= inv;
            s_prob[warp][e] = p[e];
            out[OUT_LOGITS + (size_t)t * NEXP + e] = acc[e];
        }
        int i1 = 0;
#pragma unroll
        for (int e = 1; e < NEXP; e++) if (p[e] > p[i1]) i1 = e;
        int i2 = (i1 == 0) ? 1 : 0;
#pragma unroll
        for (int e = 0; e < NEXP; e++) if (e != i2 && e != i1 && p[e] > p[i2]) i2 = e;
        float s2 = p[i1] + p[i2];
        float w1 = p[i1] / s2, w2 = p[i2] / s2;
        int pos1 = atomicAdd(&g_count[i1], 1);
        g_list[i1 * T_TOK + pos1] = t; g_wgt[i1 * T_TOK + pos1] = w1;
        int pos2 = atomicAdd(&g_count[i2], 1);
        g_list[i2 * T_TOK + pos2] = t; g_wgt[i2 * T_TOK + pos2] = w2;
    }
    __syncthreads();
    if (threadIdx.x == 0) {
        float ps[NEXP]; float l2 = 0.f;
#pragma unroll
        for (int e = 0; e < NEXP; e++) ps[e] = 0.f;
        for (int w = 0; w < 8; w++) {
            l2 += s_lse2[w];
#pragma unroll
            for (int e = 0; e < NEXP; e++) ps[e] += s_prob[w][e];
        }
#pragma unroll
        for (int e = 0; e < NEXP; e++) g_pp[blockIdx.x * NEXP + e] = ps[e];
        g_pl[blockIdx.x] = l2;
    }
}

// ---------------- finalize ----------------------------------------------------
__global__ void finalize_kernel(float* __restrict__ out) {
    const int warp = threadIdx.x >> 5, lane = threadIdx.x & 31;
    __shared__ float red[NEXP + 1];
    if (warp < NEXP) {
        float s = 0.f;
        for (int j = 0; j < ROUTER_BLOCKS / 32; j++)
            s += g_pp[(size_t)(lane + 32 * j) * NEXP + warp];
#pragma unroll
        for (int off = 16; off > 0; off >>= 1) s += __shfl_xor_sync(0xFFFFFFFFu, s, off);
        if (lane == 0) red[warp] = s;
    } else if (warp == NEXP) {
        float s = 0.f;
        for (int j = 0; j < ROUTER_BLOCKS / 32; j++)
            s += g_pl[lane + 32 * j];
#pragma unroll
        for (int off = 16; off > 0; off >>= 1) s += __shfl_xor_sync(0xFFFFFFFFu, s, off);
        if (lane == 0) red[NEXP] = s;
    }
    __syncthreads();
    if (threadIdx.x == 0) {
        float aux = 0.f;
        int rb = 0;
        for (int e = 0; e < NEXP; e++) {
            aux += ((float)g_count[e] / (float)(T_TOK * TOPK)) * (red[e] / (float)T_TOK);
            g_rowbase[e] = rb;
            rb += g_count[e];
        }
        g_rowbase[NEXP] = NROWS_ROUTED;
        out[OUT_AUX] = (float)NEXP * aux;
        out[OUT_Z]   = red[NEXP] / (float)T_TOK;
    }
}

// ---------------- compact -----------------------------------------------------
__global__ void compact_kernel() {
    int idx = blockIdx.x * blockDim.x + threadIdx.x;
    int e = idx / T_TOK, pos = idx % T_TOK;
    if (e < NEXP) {
        if (pos < g_count[e]) {
            int cr = g_rowbase[e] + pos;
            g_ctok[cr] = g_list[e * T_TOK + pos];
            g_cwgt[cr] = g_wgt[e * T_TOK + pos];
        }
    } else {
        g_ctok[NROWS_ROUTED + pos] = pos;
        g_cwgt[NROWS_ROUTED + pos] = 1.f;
    }
}

// ---------------- unified transpose+cvt: [K][N] f32 -> [N][K] fp16 ------------
// 64-K x 64-N tile (16.6KB SMEM). Reads: 4x LDG.128/thread (256B rows).
// Writes: 8x half2/thread, 128B fp16 rows. 512 blocks per z-slice.
// z: 0..7 gate, 8..15 up, 16 sgate, 17 sup (K=HDIM,N=IDIM)
//    18..25 down, 26 sdown                 (K=IDIM,N=HDIM)
__global__ void __launch_bounds__(256) cvt_w_kernel(
    const float* __restrict__ gate_w, const float* __restrict__ up_w,
    const float* __restrict__ sg_w,   const float* __restrict__ su_w,
    const float* __restrict__ down_w, const float* __restrict__ sd_w)
{
    const int z = blockIdx.y;
    const int b = blockIdx.x;           // 0..511
    const float* src; __half* dst; int K, N, n0, k0;
    if (z < 18) {
        K = HDIM; N = IDIM;
        n0 = (b & 31) * 64; k0 = (b >> 5) * 64;
        if (z < 8)        { src = gate_w + (size_t)z * HDIM * IDIM;       dst = g_gWt + (size_t)z * IDIM * HDIM; }
        else if (z < 16)  { src = up_w + (size_t)(z - 8) * HDIM * IDIM;   dst = g_uWt + (size_t)(z - 8) * IDIM * HDIM; }
        else if (z == 16) { src = sg_w; dst = g_sgWt; }
        else              { src = su_w; dst = g_suWt; }
    } else {
        K = IDIM; N = HDIM;
        n0 = (b & 15) * 64; k0 = (b >> 4) * 64;
        const int zz = z - 18;
        if (zz < 8) { src = down_w + (size_t)zz * IDIM * HDIM; dst = g_dWt + (size_t)zz * HDIM * IDIM; }
        else        { src = sd_w;  dst = g_sdWt; }
    }

    __shared__ float t[64][65];
    const int tid = threadIdx.x;
    // read phase: 1024 float4 per tile (64 rows x 16), 4 per thread
#pragma unroll
    for (int c = 0; c < 4; c++) {
        int idx = c * 256 + tid;
        int r = idx >> 4, q = idx & 15;
        float4 v = *(const float4*)(src + (size_t)(k0 + r) * N + n0 + q * 4);
        t[r][q * 4 + 0] = v.x;
        t[r][q * 4 + 1] = v.y;
        t[r][q * 4 + 2] = v.z;
        t[r][q * 4 + 3] = v.w;
    }
    __syncthreads();
    // write phase: 128B fp16 rows (64 rows, 8 per ty-group)
    const int tx = tid & 31, ty = tid >> 5;
#pragma unroll
    for (int i = 0; i < 64; i += 8) {
        float a = t[2 * tx][ty + i];
        float c = t[2 * tx + 1][ty + i];
        *(__half2*)&dst[(size_t)(n0 + ty + i) * K + k0 + 2 * tx] =
            __floats2half2_rn(a, c);
    }
}

// ============================================================================
// fp16 fused gate+up+act GEMM. 512 thr (16 warps, 4m x 4n), block 128x128,
// warp 32x32 each. K-tile 64, 3-stage cp.async pipeline, one barrier per kt.
// ============================================================================
#define PADH 72
#define TILE_H (128 * PADH)
#define NSTG 3
#define GU_SMEMB (NSTG * 3 * TILE_H * 2)   // 165888 B
#define DN_SMEMB (NSTG * 2 * TILE_H * 2)   // 110592 B

__global__ void __launch_bounds__(512, 1) gemm_gu_f16(void)
{
    const int e = blockIdx.z;
    const int n_e = (e < NEXP) ? g_count[e] : T_TOK;
    const int m0 = blockIdx.y * 128;
    if (m0 >= n_e) return;
    const int base = g_rowbase[e];
    const __half* __restrict__ Bg = (e < NEXP) ? (g_gWt + (size_t)e * IDIM * HDIM) : g_sgWt;
    const __half* __restrict__ Bu = (e < NEXP) ? (g_uWt + (size_t)e * IDIM * HDIM) : g_suWt;
    const int n0 = blockIdx.x * 128;

    const int tid  = threadIdx.x;
    const int warp = tid >> 5, lane = tid & 31;
    const int gi = lane >> 2, tig = lane & 3;
    const int wm = (warp & 3) * 32, wn = (warp >> 2) * 32;

    extern __shared__ __half sh[];
    __half* As  = sh;
    __half* Bgs = sh + NSTG * TILE_H;
    __half* Bus = sh + 2 * NSTG * TILE_H;
    const uint32_t uA = (uint32_t)__cvta_generic_to_shared(As);
    const uint32_t uG = (uint32_t)__cvta_generic_to_shared(Bgs);
    const uint32_t uU = (uint32_t)__cvta_generic_to_shared(Bus);

    const int pr0 = tid >> 3, pch = tid & 7;
    const __half* arow0;
    const __half* arow1;
    {
        int t0 = (m0 + pr0 < n_e)      ? g_ctok[base + m0 + pr0]      : g_ctok[base];
        int t1 = (m0 + pr0 + 64 < n_e) ? g_ctok[base + m0 + pr0 + 64] : g_ctok[base];
        arow0 = g_Xh + (size_t)t0 * HDIM + pch * 8;
        arow1 = g_Xh + (size_t)t1 * HDIM + pch * 8;
    }
    const __half* bgrow = Bg + (size_t)(n0 + pr0) * HDIM + pch * 8;
    const __half* burow = Bu + (size_t)(n0 + pr0) * HDIM + pch * 8;
    const size_t BROW64 = (size_t)64 * HDIM;
    const uint32_t d0 = (uint32_t)(pr0 * PADH + pch * 8) * 2;
    const uint32_t d1 = d0 + (uint32_t)(64 * PADH) * 2;

    float dg[2][4][4], du[2][4][4];
#pragma unroll
    for (int i = 0; i < 2; i++)
#pragma unroll
        for (int j = 0; j < 4; j++)
#pragma unroll
            for (int c = 0; c < 4; c++) { dg[i][j][c] = 0.f; du[i][j][c] = 0.f; }

    auto issue = [&](int kt, int s) {
        const int ko = kt * 64;
        const uint32_t bo = (uint32_t)(s * TILE_H * 2);
        cp_async16(uA + bo + d0, arow0 + ko);
        cp_async16(uA + bo + d1, arow1 + ko);
        cp_async16(uG + bo + d0, bgrow + ko);
        cp_async16(uG + bo + d1, bgrow + BROW64 + ko);
        cp_async16(uU + bo + d0, burow + ko);
        cp_async16(uU + bo + d1, burow + BROW64 + ko);
        cp_commit();
    };

    const int NK = HDIM / 64;   // 16
    issue(0, 0);
    issue(1, 1);
    int sbuf = 0;
    for (int kt = 0; kt < NK; kt++) {
        if (kt + 1 < NK) cp_wait<1>(); else cp_wait<0>();
        __syncthreads();
        if (kt + 2 < NK) {
            int s2 = sbuf + 2; if (s2 >= NSTG) s2 -= NSTG;
            issue(kt + 2, s2);
        }
        const __half* Ab = As  + sbuf * TILE_H;
        const __half* Gb = Bgs + sbuf * TILE_H;
        const __half* Ub = Bus + sbuf * TILE_H;
#pragma unroll
        for (int ks = 0; ks < 4; ks++) {
            const int kc = ks * 16 + 2 * tig;
            uint32_t af[2][4];
#pragma unroll
            for (int ms = 0; ms < 2; ms++) {
                const int mB = wm + ms * 16;
                af[ms][0] = *(const uint32_t*)&Ab[(mB + gi)     * PADH + kc];
                af[ms][1] = *(const uint32_t*)&Ab[(mB + 8 + gi) * PADH + kc];
                af[ms][2] = *(const uint32_t*)&Ab[(mB + gi)     * PADH + kc + 8];
                af[ms][3] = *(const uint32_t*)&Ab[(mB + 8 + gi) * PADH + kc + 8];
            }
            uint32_t bf[4][2];
#pragma unroll
            for (int ns = 0; ns < 4; ns++) {
                const int nB = wn + ns * 8 + gi;
                bf[ns][0] = *(const uint32_t*)&Gb[nB * PADH + kc];
                bf[ns][1] = *(const uint32_t*)&Gb[nB * PADH + kc + 8];
            }
#pragma unroll
            for (int ms = 0; ms < 2; ms++)
#pragma unroll
                for (int ns = 0; ns < 4; ns++)
                    mma_f16(dg[ms][ns], af[ms], bf[ns]);
#pragma unroll
            for (int ns = 0; ns < 4; ns++) {
                const int nB = wn + ns * 8 + gi;
                bf[ns][0] = *(const uint32_t*)&Ub[nB * PADH + kc];
                bf[ns][1] = *(const uint32_t*)&Ub[nB * PADH + kc + 8];
            }
#pragma unroll
            for (int ms = 0; ms < 2; ms++)
#pragma unroll
                for (int ns = 0; ns < 4; ns++)
                    mma_f16(du[ms][ns], af[ms], bf[ns]);
        }
        if (++sbuf == NSTG) sbuf = 0;
    }

#pragma unroll
    for (int ms = 0; ms < 2; ms++) {
#pragma unroll
        for (int hh = 0; hh < 2; hh++) {
            const int r = m0 + wm + ms * 16 + hh * 8 + gi;
            if (r < n_e) {
                const int row = base + r;
                const float w = g_cwgt[row];
                __half* C = g_Gh + (size_t)row * IDIM + n0 + wn;
#pragma unroll
                for (int ns = 0; ns < 4; ns++) {
                    float g0 = dg[ms][ns][2 * hh],     g1 = dg[ms][ns][2 * hh + 1];
                    float u0 = du[ms][ns][2 * hh],     u1 = du[ms][ns][2 * hh + 1];
                    float h0 = w * u0 * g0 / (1.f + __expf(-g0));
                    float h1 = w * u1 * g1 / (1.f + __expf(-g1));
                    *(__half2*)(C + ns * 8 + 2 * tig) = __floats2half2_rn(h0, h1);
                }
            }
        }
    }
}

// ============================================================================
// fp16 down GEMM + scatter. 256 thr (8 warps, 4m x 2n), warp 32x64,
// 2 CTAs/SM. K-tile 64, 3-stage pipeline. Epilogue: vectorized red.v2.f32.
// ============================================================================
__global__ void __launch_bounds__(256, 2) gemm_down_f16(float* __restrict__ out)
{
    const int e = blockIdx.z;
    const int n_e = (e < NEXP) ? g_count[e] : T_TOK;
    const int m0 = blockIdx.y * 128;
    if (m0 >= n_e) return;
    const int base = g_rowbase[e];
    const __half* __restrict__ B = (e < NEXP) ? (g_dWt + (size_t)e * HDIM * IDIM) : g_sdWt;
    const int n0 = blockIdx.x * 128;

    const int tid  = threadIdx.x;
    const int warp = tid >> 5, lane = tid & 31;
    const int gi = lane >> 2, tig = lane & 3;
    const int wm = (warp & 3) * 32, wn = (warp >> 2) * 64;

    extern __shared__ __half sh[];
    __half* As = sh;
    __half* Bs = sh + NSTG * TILE_H;
    const uint32_t uA = (uint32_t)__cvta_generic_to_shared(As);
    const uint32_t uB = (uint32_t)__cvta_generic_to_shared(Bs);

    const int pr0 = tid >> 3, pch = tid & 7;
    const __half* arow = g_Gh + (size_t)(base + m0 + pr0) * IDIM + pch * 8;
    const __half* brow = B + (size_t)(n0 + pr0) * IDIM + pch * 8;
    const size_t ROW32 = (size_t)32 * IDIM;
    const uint32_t ds0 = (uint32_t)(pr0 * PADH + pch * 8) * 2;
    const uint32_t SROW32 = (uint32_t)(32 * PADH) * 2;

    float d[2][8][4];
#pragma unroll
    for (int i = 0; i < 2; i++)
#pragma unroll
        for (int j = 0; j < 8; j++)
#pragma unroll
            for (int c = 0; c < 4; c++) d[i][j][c] = 0.f;

    auto issue = [&](int kt, int s) {
        const int ko = kt * 64;
        const uint32_t bo = (uint32_t)(s * TILE_H * 2);
#pragma unroll
        for (int c = 0; c < 4; c++) {
            cp_async16(uA + bo + ds0 + c * SROW32, arow + c * ROW32 + ko);
            cp_async16(uB + bo + ds0 + c * SROW32, brow + c * ROW32 + ko);
        }
        cp_commit();
    };

    const int NK = IDIM / 64;   // 32
    issue(0, 0);
    issue(1, 1);
    int sbuf = 0;
    for (int kt = 0; kt < NK; kt++) {
        if (kt + 1 < NK) cp_wait<1>(); else cp_wait<0>();
        __syncthreads();
        if (kt + 2 < NK) {
            int s2 = sbuf + 2; if (s2 >= NSTG) s2 -= NSTG;
            issue(kt + 2, s2);
        }
        const __half* Ab = As + sbuf * TILE_H;
        const __half* Bb = Bs + sbuf * TILE_H;
#pragma unroll
        for (int ks = 0; ks < 4; ks++) {
            const int kc = ks * 16 + 2 * tig;
            uint32_t af[2][4];
#pragma unroll
            for (int ms = 0; ms < 2; ms++) {
                const int mB = wm + ms * 16;
                af[ms][0] = *(const uint32_t*)&Ab[(mB + gi)     * PADH + kc];
                af[ms][1] = *(const uint32_t*)&Ab[(mB + 8 + gi) * PADH + kc];
                af[ms][2] = *(const uint32_t*)&Ab[(mB + gi)     * PADH + kc + 8];
                af[ms][3] = *(const uint32_t*)&Ab[(mB + 8 + gi) * PADH + kc + 8];
            }
            uint32_t bf[8][2];
#pragma unroll
            for (int ns = 0; ns < 8; ns++) {
                const int nB = wn + ns * 8 + gi;
                bf[ns][0] = *(const uint32_t*)&Bb[nB * PADH + kc];
                bf[ns][1] = *(const uint32_t*)&Bb[nB * PADH + kc + 8];
            }
#pragma unroll
            for (int ms = 0; ms < 2; ms++)
#pragma unroll
                for (int ns = 0; ns < 8; ns++)
                    mma_f16(d[ms][ns], af[ms], bf[ns]);
        }
        if (++sbuf == NSTG) sbuf = 0;
    }

    // epilogue: vectorized scatter-accumulate (red.v2.f32; 8B-aligned pairs)
#pragma unroll
    for (int ms = 0; ms < 2; ms++) {
        const int r0 = m0 + wm + ms * 16 + gi;
        const int r1 = r0 + 8;
        if (r0 < n_e) {
            const int tok = g_ctok[base + r0];
            float* o = out + (size_t)tok * HDIM + n0 + wn;
#pragma unroll
            for (int ns = 0; ns < 8; ns++)
                red_add_f32x2(o + ns * 8 + 2 * tig, d[ms][ns][0], d[ms][ns][1]);
        }
        if (r1 < n_e) {
            const int tok = g_ctok[base + r1];
            float* o = out + (size_t)tok * HDIM + n0 + wn;
#pragma unroll
            for (int ns = 0; ns < 8; ns++)
                red_add_f32x2(o + ns * 8 + 2 * tig, d[ms][ns][2], d[ms][ns][3]);
        }
    }
}

// ---------------- host launcher ----------------------------------------------
extern "C" void kernel_launch(void* const* d_in, const int* in_sizes, int n_in,
                              void* d_out, int out_size)
{
    const float* x       = (const float*)d_in[0];
    const float* rw      = (const float*)d_in[1];
    const float* gate_w  = (const float*)d_in[2];
    const float* up_w    = (const float*)d_in[3];
    const float* down_w  = (const float*)d_in[4];
    const float* sgate_w = (const float*)d_in[5];
    const float* sup_w   = (const float*)d_in[6];
    const float* sdown_w = (const float*)d_in[7];
    float* out = (float*)d_out;

    void* cnt_addr = nullptr;
    cudaGetSymbolAddress(&cnt_addr, g_count);

    cudaFuncSetAttribute(gemm_gu_f16,
                         cudaFuncAttributeMaxDynamicSharedMemorySize, GU_SMEMB);
    cudaFuncSetAttribute(gemm_down_f16,
                         cudaFuncAttributeMaxDynamicSharedMemorySize, DN_SMEMB);

    dim3 grid_gu(IDIM / 128, T_TOK / 128, NEXP + 1);
    dim3 grid_dn(HDIM / 128, T_TOK / 128, NEXP + 1);

    // single-stream schedule: nothing overlaps the GEMMs
    cudaMemsetAsync(out, 0, (size_t)T_TOK * HDIM * sizeof(float));
    cudaMemsetAsync(cnt_addr, 0, NEXP * sizeof(int));
    router_kernel<<<ROUTER_BLOCKS, 256>>>(x, rw, out);
    finalize_kernel<<<1, 288>>>(out);
    compact_kernel<<<((NEXP + 1) * T_TOK) / 256, 256>>>();
    cvt_w_kernel<<<dim3(512, 27), 256>>>(gate_w, up_w, sgate_w, sup_w,
                                         down_w, sdown_w);
    gemm_gu_f16<<<grid_gu, 512, GU_SMEMB>>>();
    gemm_down_f16<<<grid_dn, 256, DN_SMEMB>>>(out);
}